// round 2
// baseline (speedup 1.0000x reference)
#include <cuda_runtime.h>
#include <cstdint>
#include <cstddef>

#define BATCH 8192
#define NNODES 25

constexpr int BN  = 128;  // batch cols per block
constexpr int BM  = 64;   // output-channel rows per block
constexpr int BKK = 16;   // K tile

// ---------------- scratch (device globals; no allocations allowed) ---------
__device__ float g_Xt[(size_t)1200 * BATCH];          //  [3*20*20][B]
__device__ float g_C1[(size_t)64  * 400 * BATCH];     //  conv1 out [64][20][20][B]
__device__ float g_P1[(size_t)64  * 100 * BATCH];     //  pool1     [64][10][10][B]
__device__ float g_C2[(size_t)128 * 100 * BATCH];     //  conv2 out
__device__ float g_P2[(size_t)128 * 25  * BATCH];     //  pool2     [128][5][5][B]
__device__ float g_C3[(size_t)256 * 25  * BATCH];     //  conv3 out
__device__ float g_C4[(size_t)256 * 25  * BATCH];     //  conv4 out = feats [c][pos][b]
__device__ float g_F [(size_t)NNODES * 600 * BATCH];  //  feats @ Wa[80:336] + ba
__device__ float g_G [(size_t)NNODES * 600 * BATCH];  //  nb @ Wa[0:80]
__device__ float g_PR[(size_t)NNODES * 10  * BATCH];  //  stage1 preds [n][c][b]
__device__ int   g_NEI[NNODES * 8];

// ---------------- neighbor table (built on device, deterministic) ----------
__global__ void nei_init_kernel() {
    int i = threadIdx.x;
    if (i >= NNODES) return;
    const int w = 5, size = 25;
    int n[8]; int cnt = 0;
    if (i - w >= 0)                               n[cnt++] = i - w;
    if (i % w != 0)                               n[cnt++] = i - 1;
    if ((i + 1) % w != 0)                         n[cnt++] = i + 1;
    if (i + w < size)                             n[cnt++] = i + w;
    if (i - w - 1 >= 0 && i % w != 0)             n[cnt++] = i - w - 1;
    if (i - w + 1 >= 0 && (i + 1) % w != 0)       n[cnt++] = i - w + 1;
    if (i + w - 1 < size && i % w != 0)           n[cnt++] = i + w - 1;
    if (i + w + 1 < size && (i + 1) % w != 0)     n[cnt++] = i + w + 1;
    while (cnt < 8) n[cnt++] = -1;
    for (int j = 0; j < 8; ++j) g_NEI[i * 8 + j] = n[j];
}

// ---------------- NCHW -> [p][b] transpose of x ----------------------------
__global__ void transpose_kernel(const float* __restrict__ x) {
    __shared__ float tile[32][33];
    const int p0 = blockIdx.x * 32;
    const int b0 = blockIdx.y * 32;
    const int tx = threadIdx.x, ty = threadIdx.y;
    #pragma unroll
    for (int i = 0; i < 32; i += 8) {
        int p = p0 + tx, b = b0 + ty + i;
        if (p < 1200) tile[ty + i][tx] = x[(size_t)b * 1200 + p];
    }
    __syncthreads();
    #pragma unroll
    for (int i = 0; i < 32; i += 8) {
        int p = p0 + ty + i, b = b0 + tx;
        if (p < 1200) g_Xt[(size_t)p * BATCH + b] = tile[tx][ty + i];
    }
}

// ---------------- generic fp32 tiled GEMM with gather modes -----------------
// MODE 0: implicit-im2col conv, epilogue BN+ReLU.  A = weights [Cout][K] row-major.
// MODE 1: F = Wa[n][80:336].T @ feats[n]  (+ba).   A col-major, B = g_C4.
// MODE 2: G = Wa[n][0:80].T @ nb[n].               A col-major, B = g_PR w/ NEI gather.
template<int MODE>
__global__ void __launch_bounds__(256, 2)
gemm_kernel(const float* __restrict__ A, const float* __restrict__ Bin,
            float* __restrict__ C, int K, int Cout,
            int H, int W,
            const float* __restrict__ bnb, const float* __restrict__ bng,
            const float* __restrict__ bnbe, const float* __restrict__ bnm,
            const float* __restrict__ bnv, const float* __restrict__ bias)
{
    __shared__ float As[BKK][BM];
    __shared__ float Bs[BKK][BN];

    const int tid  = threadIdx.x;
    const int b0   = blockIdx.x * BN;
    const int row0 = blockIdx.z * BM;
    const int yb   = blockIdx.y;      // conv: spatial pos ; mlp: node

    int oy = 0, ox = 0;
    if (MODE == 0) { oy = yb / W; ox = yb - oy * W; }

    const float* Ab;
    if (MODE == 0)      Ab = A;
    else if (MODE == 1) Ab = A + (size_t)yb * 336 * 600 + 80 * 600;
    else                Ab = A + (size_t)yb * 336 * 600;

    const int crow = (tid >> 4) << 2;     // 0..60
    const int c0   = (tid & 15) << 2;     // 0..60 (cols c0..c0+3 and 64+c0..64+c0+3)

    float acc[4][8];
    #pragma unroll
    for (int i = 0; i < 4; ++i)
        #pragma unroll
        for (int j = 0; j < 8; ++j) acc[i][j] = 0.f;

    const int nk = (K + BKK - 1) / BKK;
    for (int kt = 0; kt < nk; ++kt) {
        const int k0 = kt * BKK;
        __syncthreads();
        // ---- A tile ----
        if (MODE == 0) {
            const int aRow = tid >> 2;
            const int aK   = (tid & 3) << 2;
            #pragma unroll
            for (int i = 0; i < 4; ++i) {
                const int kk = k0 + aK + i;
                As[aK + i][aRow] = (kk < K) ? Ab[(size_t)(row0 + aRow) * K + kk] : 0.f;
            }
        } else {
            const int aK = tid >> 4;
            const int aR = (tid & 15) << 2;
            const int r  = row0 + aR;
            float4 v = make_float4(0.f, 0.f, 0.f, 0.f);
            if (r < Cout) v = *(const float4*)(Ab + (size_t)(k0 + aK) * 600 + r);
            As[aK][aR] = v.x; As[aK][aR + 1] = v.y; As[aK][aR + 2] = v.z; As[aK][aR + 3] = v.w;
        }
        // ---- B tile (gathered) ----
        #pragma unroll
        for (int i = 0; i < 2; ++i) {
            const int f  = tid + i * 256;
            const int bk = f >> 5;
            const int bc = (f & 31) << 2;
            const int kk = k0 + bk;
            float4 v = make_float4(0.f, 0.f, 0.f, 0.f);
            if (MODE == 0) {
                if (kk < K) {
                    const int ci = kk / 9, r9 = kk - ci * 9;
                    const int ky = r9 / 3, kx = r9 - ky * 3;
                    const int iy = oy + ky - 1, ix = ox + kx - 1;
                    if ((unsigned)iy < (unsigned)H && (unsigned)ix < (unsigned)W)
                        v = *(const float4*)(Bin + (size_t)((ci * H + iy) * W + ix) * BATCH + b0 + bc);
                }
            } else if (MODE == 1) {
                v = *(const float4*)(Bin + ((size_t)kk * NNODES + yb) * BATCH + b0 + bc);
            } else {
                const int slot = kk / 10, cc = kk - slot * 10;
                const int mn = g_NEI[yb * 8 + slot];
                if (mn >= 0)
                    v = *(const float4*)(Bin + (size_t)(mn * 10 + cc) * BATCH + b0 + bc);
            }
            *(float4*)(&Bs[bk][bc]) = v;
        }
        __syncthreads();
        // ---- compute ----
        #pragma unroll
        for (int k = 0; k < BKK; ++k) {
            const float a0 = As[k][crow], a1 = As[k][crow + 1];
            const float a2 = As[k][crow + 2], a3 = As[k][crow + 3];
            float bl[8];
            #pragma unroll
            for (int j = 0; j < 4; ++j) bl[j]     = Bs[k][c0 + j];
            #pragma unroll
            for (int j = 0; j < 4; ++j) bl[4 + j] = Bs[k][64 + c0 + j];
            #pragma unroll
            for (int j = 0; j < 8; ++j) {
                acc[0][j] = fmaf(a0, bl[j], acc[0][j]);
                acc[1][j] = fmaf(a1, bl[j], acc[1][j]);
                acc[2][j] = fmaf(a2, bl[j], acc[2][j]);
                acc[3][j] = fmaf(a3, bl[j], acc[3][j]);
            }
        }
    }

    // ---- epilogue ----
    const size_t rowStride = (MODE == 0) ? (size_t)H * W * BATCH : (size_t)BATCH;
    float* Cb = (MODE == 0) ? C + (size_t)yb * BATCH + b0
                            : C + (size_t)yb * 600 * BATCH + b0;
    #pragma unroll
    for (int i = 0; i < 4; ++i) {
        const int r = row0 + crow + i;
        if (r >= Cout) continue;
        float alpha = 1.f, beta = 0.f;
        if (MODE == 0) {
            const float s = bng[r] * rsqrtf(bnv[r] + 1e-5f);
            alpha = s;
            beta  = (bnb[r] - bnm[r]) * s + bnbe[r];
        } else if (MODE == 1) {
            beta = bias[yb * 600 + r];
        }
        float* Cr = Cb + (size_t)r * rowStride;
        float4 v0, v1;
        v0.x = acc[i][0] * alpha + beta;  v0.y = acc[i][1] * alpha + beta;
        v0.z = acc[i][2] * alpha + beta;  v0.w = acc[i][3] * alpha + beta;
        v1.x = acc[i][4] * alpha + beta;  v1.y = acc[i][5] * alpha + beta;
        v1.z = acc[i][6] * alpha + beta;  v1.w = acc[i][7] * alpha + beta;
        if (MODE == 0) {
            v0.x = fmaxf(v0.x, 0.f); v0.y = fmaxf(v0.y, 0.f);
            v0.z = fmaxf(v0.z, 0.f); v0.w = fmaxf(v0.w, 0.f);
            v1.x = fmaxf(v1.x, 0.f); v1.y = fmaxf(v1.y, 0.f);
            v1.z = fmaxf(v1.z, 0.f); v1.w = fmaxf(v1.w, 0.f);
        }
        *(float4*)(Cr + c0)      = v0;
        *(float4*)(Cr + 64 + c0) = v1;
    }
}

// ---------------- maxpool 3x3 s2 p1 on [C][Hi][Wi][B] ----------------------
__global__ void pool_kernel(const float* __restrict__ In, float* __restrict__ Out,
                            int C, int Hi, int Wi, int Ho, int Wo)
{
    const size_t total = (size_t)C * Ho * Wo * BATCH;
    size_t idx = (size_t)blockIdx.x * blockDim.x + threadIdx.x;
    if (idx >= total) return;
    const int b = idx & (BATCH - 1);
    size_t t = idx >> 13;                 // BATCH = 8192 = 2^13
    const int ox = t % Wo; t /= Wo;
    const int oy = t % Ho; const int c = (int)(t / Ho);
    float mx = __int_as_float(0xff800000);   // -inf
    #pragma unroll
    for (int ky = 0; ky < 3; ++ky) {
        const int iy = 2 * oy - 1 + ky;
        if ((unsigned)iy >= (unsigned)Hi) continue;
        #pragma unroll
        for (int kx = 0; kx < 3; ++kx) {
            const int ix = 2 * ox - 1 + kx;
            if ((unsigned)ix >= (unsigned)Wi) continue;
            mx = fmaxf(mx, In[(size_t)((c * Hi + iy) * Wi + ix) * BATCH + b]);
        }
    }
    Out[idx] = mx;
}

// ---------------- MLP head: tanh(+)·Wb + bb, softmax ------------------------
// STAGE 1: reads F, writes preds [n][c][b].  STAGE 2: reads F+G, writes second [n][b][c].
template<int STAGE>
__global__ void __launch_bounds__(256)
head_kernel(const float* __restrict__ Fin, const float* __restrict__ Gin,
            const float* __restrict__ Wb, const float* __restrict__ bb,
            float* __restrict__ out)
{
    __shared__ float Wbs[6000];
    __shared__ float bbs[10];
    const int n = blockIdx.y;
    const int b = blockIdx.x * 256 + threadIdx.x;
    const float* Wbn = Wb + (size_t)n * 6000;
    for (int i = threadIdx.x; i < 6000; i += 256) Wbs[i] = Wbn[i];
    if (threadIdx.x < 10) bbs[threadIdx.x] = bb[n * 10 + threadIdx.x];
    __syncthreads();

    float acc[10];
    #pragma unroll
    for (int c = 0; c < 10; ++c) acc[c] = bbs[c];

    const float* Fp = Fin + (size_t)n * 600 * BATCH + b;
    const float* Gp = (STAGE == 2) ? (Gin + (size_t)n * 600 * BATCH + b) : nullptr;
    for (int h = 0; h < 600; ++h) {
        float v = Fp[(size_t)h * BATCH];
        if (STAGE == 2) v += Gp[(size_t)h * BATCH];
        v = tanhf(v);
        #pragma unroll
        for (int c = 0; c < 10; ++c) acc[c] = fmaf(v, Wbs[h * 10 + c], acc[c]);
    }
    float mx = acc[0];
    #pragma unroll
    for (int c = 1; c < 10; ++c) mx = fmaxf(mx, acc[c]);
    float s = 0.f;
    #pragma unroll
    for (int c = 0; c < 10; ++c) { acc[c] = expf(acc[c] - mx); s += acc[c]; }
    const float inv = 1.f / s;
    if (STAGE == 1) {
        #pragma unroll
        for (int c = 0; c < 10; ++c) out[(size_t)(n * 10 + c) * BATCH + b] = acc[c] * inv;
    } else {
        #pragma unroll
        for (int c = 0; c < 10; ++c) out[((size_t)n * BATCH + b) * 10 + c] = acc[c] * inv;
    }
}

// ---------------- mean over 25 nodes ---------------------------------------
__global__ void mean_kernel(const float* __restrict__ second, float* __restrict__ mout) {
    const int idx = blockIdx.x * 256 + threadIdx.x;   // b*10 + c
    if (idx >= BATCH * 10) return;
    float s = 0.f;
    #pragma unroll
    for (int n = 0; n < NNODES; ++n) s += second[(size_t)n * BATCH * 10 + idx];
    mout[idx] = s * (1.f / 25.f);
}

// ---------------- launch ----------------------------------------------------
extern "C" void kernel_launch(void* const* d_in, const int* in_sizes, int n_in,
                              void* d_out, int out_size)
{
    const float* x  = (const float*)d_in[0];
    const float* W1 = (const float*)d_in[1];
    const float* b1 = (const float*)d_in[2];
    const float* g1 = (const float*)d_in[3];
    const float* be1= (const float*)d_in[4];
    const float* m1 = (const float*)d_in[5];
    const float* v1 = (const float*)d_in[6];
    const float* W2 = (const float*)d_in[7];
    const float* b2 = (const float*)d_in[8];
    const float* g2 = (const float*)d_in[9];
    const float* be2= (const float*)d_in[10];
    const float* m2 = (const float*)d_in[11];
    const float* v2 = (const float*)d_in[12];
    const float* W3 = (const float*)d_in[13];
    const float* b3 = (const float*)d_in[14];
    const float* g3 = (const float*)d_in[15];
    const float* be3= (const float*)d_in[16];
    const float* m3 = (const float*)d_in[17];
    const float* v3 = (const float*)d_in[18];
    const float* W4 = (const float*)d_in[19];
    const float* b4 = (const float*)d_in[20];
    const float* g4 = (const float*)d_in[21];
    const float* be4= (const float*)d_in[22];
    const float* m4 = (const float*)d_in[23];
    const float* v4 = (const float*)d_in[24];
    const float* Wa = (const float*)d_in[25];
    const float* ba = (const float*)d_in[26];
    const float* Wb = (const float*)d_in[27];
    const float* bb = (const float*)d_in[28];

    float *Xt, *C1, *P1, *C2, *P2, *C3, *C4, *F, *G, *PR;
    cudaGetSymbolAddress((void**)&Xt, g_Xt);
    cudaGetSymbolAddress((void**)&C1, g_C1);
    cudaGetSymbolAddress((void**)&P1, g_P1);
    cudaGetSymbolAddress((void**)&C2, g_C2);
    cudaGetSymbolAddress((void**)&P2, g_P2);
    cudaGetSymbolAddress((void**)&C3, g_C3);
    cudaGetSymbolAddress((void**)&C4, g_C4);
    cudaGetSymbolAddress((void**)&F,  g_F);
    cudaGetSymbolAddress((void**)&G,  g_G);
    cudaGetSymbolAddress((void**)&PR, g_PR);

    float* out = (float*)d_out;
    float* second = out + BATCH * 10;

    nei_init_kernel<<<1, 32>>>();
    transpose_kernel<<<dim3(38, 256), dim3(32, 8)>>>(x);

    // conv1 (3->64, 20x20)
    gemm_kernel<0><<<dim3(64, 400, 1), 256>>>(W1, Xt, C1, 27, 64, 20, 20,
                                              b1, g1, be1, m1, v1, nullptr);
    pool_kernel<<<(int)(((size_t)64 * 100 * BATCH + 255) / 256), 256>>>(C1, P1, 64, 20, 20, 10, 10);

    // conv2 (64->128, 10x10)
    gemm_kernel<0><<<dim3(64, 100, 2), 256>>>(W2, P1, C2, 576, 128, 10, 10,
                                              b2, g2, be2, m2, v2, nullptr);
    pool_kernel<<<(int)(((size_t)128 * 25 * BATCH + 255) / 256), 256>>>(C2, P2, 128, 10, 10, 5, 5);

    // conv3 (128->256, 5x5)
    gemm_kernel<0><<<dim3(64, 25, 4), 256>>>(W3, P2, C3, 1152, 256, 5, 5,
                                             b3, g3, be3, m3, v3, nullptr);
    // conv4 (256->256, 5x5)
    gemm_kernel<0><<<dim3(64, 25, 4), 256>>>(W4, C3, C4, 2304, 256, 5, 5,
                                             b4, g4, be4, m4, v4, nullptr);

    // F[n] = Wa[n][80:336].T @ feats[n] + ba[n]   (shared by both stages)
    gemm_kernel<1><<<dim3(64, 25, 10), 256>>>(Wa, C4, F, 256, 600, 0, 0,
                                              nullptr, nullptr, nullptr, nullptr, nullptr, ba);
    // stage 1 predictions
    head_kernel<1><<<dim3(32, 25), 256>>>(F, nullptr, Wb, bb, PR);
    // G[n] = Wa[n][0:80].T @ neighbor-preds[n]
    gemm_kernel<2><<<dim3(64, 25, 10), 256>>>(Wa, PR, G, 80, 600, 0, 0,
                                              nullptr, nullptr, nullptr, nullptr, nullptr, nullptr);
    // stage 2 -> second [25][B][10] into d_out
    head_kernel<2><<<dim3(32, 25), 256>>>(F, G, Wb, bb, second);
    // mean over nodes -> first B*10 of d_out
    mean_kernel<<<(BATCH * 10 + 255) / 256, 256>>>(second, out);
}

// round 5
// speedup vs baseline: 2.1512x; 2.1512x over previous
#include <cuda_runtime.h>
#include <cuda_bf16.h>
#include <cstdint>
#include <cstddef>

#define BATCH 8192
#define NNODES 25

constexpr int BN  = 128;
constexpr int BM  = 64;
constexpr int BKK = 16;

// ---------------- scratch (device globals; no allocations allowed) ---------
__device__ float g_Xt[(size_t)1200 * BATCH];
__device__ float g_C1[(size_t)64  * 400 * BATCH];
__device__ float g_P1[(size_t)64  * 100 * BATCH];
__device__ float g_C2[(size_t)128 * 100 * BATCH];
__device__ float g_P2[(size_t)128 * 25  * BATCH];
__device__ float g_C3[(size_t)256 * 25  * BATCH];
__device__ float g_C4[(size_t)256 * 25  * BATCH];
__device__ float g_F [(size_t)NNODES * 600 * BATCH];
__device__ float g_G [(size_t)NNODES * 600 * BATCH];
__device__ float g_PR[(size_t)NNODES * 10  * BATCH];
__device__ int   g_NEI[NNODES * 8];

// ======================= helpers ===========================================
__device__ __forceinline__ uint32_t s2u(const void* p) {
    uint32_t a;
    asm("{ .reg .u64 t; cvta.to.shared.u64 t, %1; cvt.u32.u64 %0, t; }"
        : "=r"(a) : "l"(p));
    return a;
}
__device__ __forceinline__ void ldsm4(uint32_t* r, uint32_t addr) {
    asm volatile("ldmatrix.sync.aligned.m8n8.x4.shared.b16 {%0,%1,%2,%3}, [%4];"
        : "=r"(r[0]), "=r"(r[1]), "=r"(r[2]), "=r"(r[3]) : "r"(addr));
}
__device__ __forceinline__ void ldsm4t(uint32_t* r, uint32_t addr) {
    asm volatile("ldmatrix.sync.aligned.m8n8.x4.trans.shared.b16 {%0,%1,%2,%3}, [%4];"
        : "=r"(r[0]), "=r"(r[1]), "=r"(r[2]), "=r"(r[3]) : "r"(addr));
}
__device__ __forceinline__ void mma16816(float* c, const uint32_t* a, const uint32_t* b) {
    asm volatile("mma.sync.aligned.m16n8k16.row.col.f32.bf16.bf16.f32 "
        "{%0,%1,%2,%3}, {%4,%5,%6,%7}, {%8,%9}, {%0,%1,%2,%3};"
        : "+f"(c[0]), "+f"(c[1]), "+f"(c[2]), "+f"(c[3])
        : "r"(a[0]), "r"(a[1]), "r"(a[2]), "r"(a[3]), "r"(b[0]), "r"(b[1]));
}
__device__ __forceinline__ uint32_t pack_bf2(float a, float b) {
    __nv_bfloat162 t = __floats2bfloat162_rn(a, b);
    return *reinterpret_cast<uint32_t*>(&t);
}
// split float4 into hi (rn) and lo (residual) packed pairs
__device__ __forceinline__ void split4(float4 v, uint2& hv, uint2& lv) {
    __nv_bfloat16 h0 = __float2bfloat16(v.x), h1 = __float2bfloat16(v.y);
    __nv_bfloat16 h2 = __float2bfloat16(v.z), h3 = __float2bfloat16(v.w);
    float l0 = v.x - __bfloat162float(h0), l1 = v.y - __bfloat162float(h1);
    float l2 = v.z - __bfloat162float(h2), l3 = v.w - __bfloat162float(h3);
    __nv_bfloat162 p0 = __halves2bfloat162(h0, h1);
    __nv_bfloat162 p1 = __halves2bfloat162(h2, h3);
    hv = make_uint2(*reinterpret_cast<uint32_t*>(&p0), *reinterpret_cast<uint32_t*>(&p1));
    lv = make_uint2(pack_bf2(l0, l1), pack_bf2(l2, l3));
}

// ======================= mma.sync split-bf16 GEMM ==========================
// Tile: M=128 (Cout rows), N=64 (batch), K=32.  8 warps (4 m x 2 n), warp 32x32.
// MODE 0: implicit-im2col conv + BN/ReLU.   A row-major [Cout][K].
// MODE 1: F = Wa[n][80:336].T @ feats + ba. A col-major stride 600.
// MODE 2: G = Wa[n][0:80].T @ nb.           A col-major, B = g_PR w/ NEI gather.
constexpr int ASTR = 40;   // bf16 per A smem row (32 + 8 pad)
constexpr int BSTR = 72;   // bf16 per B smem row (64 + 8 pad)

template<int MODE>
__global__ void __launch_bounds__(256, 2)
mma_gemm(const float* __restrict__ A, const float* __restrict__ Bin,
         float* __restrict__ C, int K, int Cout, int H, int W,
         const float* __restrict__ bnb, const float* __restrict__ bng,
         const float* __restrict__ bnbe, const float* __restrict__ bnm,
         const float* __restrict__ bnv, const float* __restrict__ bias)
{
    __shared__ __align__(16) __nv_bfloat16 sAh[128 * ASTR], sAl[128 * ASTR];
    __shared__ __align__(16) __nv_bfloat16 sBh[32 * BSTR],  sBl[32 * BSTR];

    const int tid = threadIdx.x, wid = tid >> 5, lid = tid & 31;
    const int yb   = blockIdx.x;
    const int bofs = blockIdx.y * 64;
    const int row0 = blockIdx.z * 128;
    const int wm = wid >> 1, wn = wid & 1;

    int oy = 0, ox = 0;
    if (MODE == 0) { oy = yb / W; ox = yb - oy * W; }
    const float* Ab = (MODE == 0) ? A
                    : (MODE == 1) ? (A + (size_t)yb * 336 * 600 + 80 * 600)
                                  : (A + (size_t)yb * 336 * 600);

    const uint32_t uAh = s2u(sAh), uAl = s2u(sAl);
    const uint32_t uBh = s2u(sBh), uBl = s2u(sBl);

    float acc[2][4][4];
    #pragma unroll
    for (int a = 0; a < 2; ++a)
        #pragma unroll
        for (int b = 0; b < 4; ++b)
            #pragma unroll
            for (int c = 0; c < 4; ++c) acc[a][b][c] = 0.f;

    const int nch = (K + 31) / 32;
    for (int kc = 0; kc < nch; ++kc) {
        const int k0 = kc * 32;
        __syncthreads();

        // ---------------- A producer ----------------
        if (MODE == 0) {
            const int r  = tid >> 1;
            const int kk = (tid & 1) * 16;
            const float4* src = (const float4*)(Ab + (size_t)(row0 + r) * K + k0 + kk);
            #pragma unroll
            for (int i = 0; i < 4; ++i) {
                uint2 hv, lv;
                split4(src[i], hv, lv);
                *(uint2*)&sAh[r * ASTR + kk + i * 4] = hv;
                *(uint2*)&sAl[r * ASTR + kk + i * 4] = lv;
            }
        } else {
            const int r  = tid & 127;
            const int kh = (tid >> 7) * 16;
            const bool okr = (row0 + r) < Cout;
            #pragma unroll
            for (int i = 0; i < 16; ++i) {
                const int k = kh + i;
                float v = 0.f;
                if (okr && (k0 + k) < K) v = Ab[(size_t)(k0 + k) * 600 + row0 + r];
                __nv_bfloat16 h = __float2bfloat16(v);
                sAh[r * ASTR + k] = h;
                sAl[r * ASTR + k] = __float2bfloat16(v - __bfloat162float(h));
            }
        }

        // ---------------- B producer ----------------
        {
            const int k  = tid >> 3;
            const int nc = (tid & 7) * 8;
            const int kk = k0 + k;
            float4 v0 = make_float4(0.f, 0.f, 0.f, 0.f);
            float4 v1 = make_float4(0.f, 0.f, 0.f, 0.f);
            if (MODE == 0) {
                const int ci = kk / 9, r9 = kk - ci * 9;
                const int ky = r9 / 3, kx = r9 - ky * 3;
                const int iy = oy + ky - 1, ix = ox + kx - 1;
                if ((unsigned)iy < (unsigned)H && (unsigned)ix < (unsigned)W) {
                    const float* p = Bin + (size_t)((ci * H + iy) * W + ix) * BATCH + bofs + nc;
                    v0 = *(const float4*)p;
                    v1 = *(const float4*)(p + 4);
                }
            } else if (MODE == 1) {
                const float* p = Bin + ((size_t)kk * NNODES + yb) * BATCH + bofs + nc;
                v0 = *(const float4*)p;
                v1 = *(const float4*)(p + 4);
            } else {
                if (kk < K) {
                    const int slot = kk / 10, cc = kk - slot * 10;
                    const int mn = g_NEI[yb * 8 + slot];
                    if (mn >= 0) {
                        const float* p = Bin + (size_t)(mn * 10 + cc) * BATCH + bofs + nc;
                        v0 = *(const float4*)p;
                        v1 = *(const float4*)(p + 4);
                    }
                }
            }
            uint2 hv, lv;
            split4(v0, hv, lv);
            *(uint2*)&sBh[k * BSTR + nc]     = hv;
            *(uint2*)&sBl[k * BSTR + nc]     = lv;
            split4(v1, hv, lv);
            *(uint2*)&sBh[k * BSTR + nc + 4] = hv;
            *(uint2*)&sBl[k * BSTR + nc + 4] = lv;
        }

        __syncthreads();

        // ---------------- compute: 2 k16 steps ----------------
        #pragma unroll
        for (int ks = 0; ks < 2; ++ks) {
            uint32_t ah[2][4], al[2][4], bh[2][4], bl[2][4];
            #pragma unroll
            for (int mt = 0; mt < 2; ++mt) {
                const uint32_t off = (uint32_t)(wm * 32 + mt * 16 + (lid & 15)) * (ASTR * 2)
                                   + ks * 32 + (lid >> 4) * 16;
                ldsm4(ah[mt], uAh + off);
                ldsm4(al[mt], uAl + off);
            }
            #pragma unroll
            for (int ng = 0; ng < 2; ++ng) {
                const uint32_t off = (uint32_t)(ks * 16 + (lid & 15)) * (BSTR * 2)
                                   + (wn * 32 + ng * 16) * 2 + (lid >> 4) * 16;
                ldsm4t(bh[ng], uBh + off);
                ldsm4t(bl[ng], uBl + off);
            }
            #pragma unroll
            for (int mt = 0; mt < 2; ++mt) {
                #pragma unroll
                for (int nt = 0; nt < 4; ++nt) {
                    const int ng = nt >> 1, p = (nt & 1) * 2;
                    mma16816(acc[mt][nt], ah[mt], &bh[ng][p]);
                    mma16816(acc[mt][nt], ah[mt], &bl[ng][p]);
                    mma16816(acc[mt][nt], al[mt], &bh[ng][p]);
                }
            }
        }
    }

    // ---------------- epilogue ----------------
    const int g  = lid >> 2;
    const int qc = (lid & 3) * 2;
    #pragma unroll
    for (int mt = 0; mt < 2; ++mt) {
        const int r0g = row0 + wm * 32 + mt * 16 + g;
        const int r1g = r0g + 8;
        float al0 = 1.f, be0 = 0.f, al1 = 1.f, be1 = 0.f;
        const bool ok0 = r0g < Cout, ok1 = r1g < Cout;
        if (MODE == 0) {
            const float s0 = bng[r0g] * rsqrtf(bnv[r0g] + 1e-5f);
            al0 = s0; be0 = (bnb[r0g] - bnm[r0g]) * s0 + bnbe[r0g];
            const float s1 = bng[r1g] * rsqrtf(bnv[r1g] + 1e-5f);
            al1 = s1; be1 = (bnb[r1g] - bnm[r1g]) * s1 + bnbe[r1g];
        } else if (MODE == 1) {
            if (ok0) be0 = bias[yb * 600 + r0g];
            if (ok1) be1 = bias[yb * 600 + r1g];
        }
        float* C0;
        float* C1;
        if (MODE == 0) {
            C0 = C + ((size_t)r0g * H * W + yb) * BATCH + bofs;
            C1 = C + ((size_t)r1g * H * W + yb) * BATCH + bofs;
        } else {
            C0 = C + ((size_t)yb * 600 + r0g) * BATCH + bofs;
            C1 = C + ((size_t)yb * 600 + r1g) * BATCH + bofs;
        }
        #pragma unroll
        for (int nt = 0; nt < 4; ++nt) {
            const int col = wn * 32 + nt * 8 + qc;
            float2 v0, v1;
            v0.x = acc[mt][nt][0] * al0 + be0;  v0.y = acc[mt][nt][1] * al0 + be0;
            v1.x = acc[mt][nt][2] * al1 + be1;  v1.y = acc[mt][nt][3] * al1 + be1;
            if (MODE == 0) {
                v0.x = fmaxf(v0.x, 0.f); v0.y = fmaxf(v0.y, 0.f);
                v1.x = fmaxf(v1.x, 0.f); v1.y = fmaxf(v1.y, 0.f);
            }
            if (ok0) *(float2*)(C0 + col) = v0;
            if (ok1) *(float2*)(C1 + col) = v1;
        }
    }
}

// ======================= SIMT kernels ======================================
__global__ void nei_init_kernel() {
    int i = threadIdx.x;
    if (i >= NNODES) return;
    const int w = 5, size = 25;
    int n[8]; int cnt = 0;
    if (i - w >= 0)                               n[cnt++] = i - w;
    if (i % w != 0)                               n[cnt++] = i - 1;
    if ((i + 1) % w != 0)                         n[cnt++] = i + 1;
    if (i + w < size)                             n[cnt++] = i + w;
    if (i - w - 1 >= 0 && i % w != 0)             n[cnt++] = i - w - 1;
    if (i - w + 1 >= 0 && (i + 1) % w != 0)       n[cnt++] = i - w + 1;
    if (i + w - 1 < size && i % w != 0)           n[cnt++] = i + w - 1;
    if (i + w + 1 < size && (i + 1) % w != 0)     n[cnt++] = i + w + 1;
    while (cnt < 8) n[cnt++] = -1;
    for (int j = 0; j < 8; ++j) g_NEI[i * 8 + j] = n[j];
}

__global__ void transpose_kernel(const float* __restrict__ x) {
    __shared__ float tile[32][33];
    const int p0 = blockIdx.x * 32;
    const int b0 = blockIdx.y * 32;
    const int tx = threadIdx.x, ty = threadIdx.y;
    #pragma unroll
    for (int i = 0; i < 32; i += 8) {
        int p = p0 + tx, b = b0 + ty + i;
        if (p < 1200) tile[ty + i][tx] = x[(size_t)b * 1200 + p];
    }
    __syncthreads();
    #pragma unroll
    for (int i = 0; i < 32; i += 8) {
        int p = p0 + ty + i, b = b0 + tx;
        if (p < 1200) g_Xt[(size_t)p * BATCH + b] = tile[tx][ty + i];
    }
}

// conv1 only (K=27)
__global__ void __launch_bounds__(256, 2)
gemm_kernel(const float* __restrict__ A, const float* __restrict__ Bin,
            float* __restrict__ C, int K, int Cout, int H, int W,
            const float* __restrict__ bnb, const float* __restrict__ bng,
            const float* __restrict__ bnbe, const float* __restrict__ bnm,
            const float* __restrict__ bnv)
{
    __shared__ float As[BKK][BM];
    __shared__ float Bs[BKK][BN];

    const int tid  = threadIdx.x;
    const int b0   = blockIdx.x * BN;
    const int row0 = blockIdx.z * BM;
    const int yb   = blockIdx.y;
    const int oy = yb / W, ox = yb - oy * W;

    const int crow = (tid >> 4) << 2;
    const int c0   = (tid & 15) << 2;

    float acc[4][8];
    #pragma unroll
    for (int i = 0; i < 4; ++i)
        #pragma unroll
        for (int j = 0; j < 8; ++j) acc[i][j] = 0.f;

    const int nk = (K + BKK - 1) / BKK;
    for (int kt = 0; kt < nk; ++kt) {
        const int k0 = kt * BKK;
        __syncthreads();
        {
            const int aRow = tid >> 2;
            const int aK   = (tid & 3) << 2;
            #pragma unroll
            for (int i = 0; i < 4; ++i) {
                const int kk = k0 + aK + i;
                As[aK + i][aRow] = (kk < K) ? A[(size_t)(row0 + aRow) * K + kk] : 0.f;
            }
        }
        #pragma unroll
        for (int i = 0; i < 2; ++i) {
            const int f  = tid + i * 256;
            const int bk = f >> 5;
            const int bc = (f & 31) << 2;
            const int kk = k0 + bk;
            float4 v = make_float4(0.f, 0.f, 0.f, 0.f);
            if (kk < K) {
                const int ci = kk / 9, r9 = kk - ci * 9;
                const int ky = r9 / 3, kx = r9 - ky * 3;
                const int iy = oy + ky - 1, ix = ox + kx - 1;
                if ((unsigned)iy < (unsigned)H && (unsigned)ix < (unsigned)W)
                    v = *(const float4*)(Bin + (size_t)((ci * H + iy) * W + ix) * BATCH + b0 + bc);
            }
            *(float4*)(&Bs[bk][bc]) = v;
        }
        __syncthreads();
        #pragma unroll
        for (int k = 0; k < BKK; ++k) {
            const float a0 = As[k][crow], a1 = As[k][crow + 1];
            const float a2 = As[k][crow + 2], a3 = As[k][crow + 3];
            float bl[8];
            #pragma unroll
            for (int j = 0; j < 4; ++j) bl[j]     = Bs[k][c0 + j];
            #pragma unroll
            for (int j = 0; j < 4; ++j) bl[4 + j] = Bs[k][64 + c0 + j];
            #pragma unroll
            for (int j = 0; j < 8; ++j) {
                acc[0][j] = fmaf(a0, bl[j], acc[0][j]);
                acc[1][j] = fmaf(a1, bl[j], acc[1][j]);
                acc[2][j] = fmaf(a2, bl[j], acc[2][j]);
                acc[3][j] = fmaf(a3, bl[j], acc[3][j]);
            }
        }
    }

    const size_t rowStride = (size_t)H * W * BATCH;
    float* Cb = C + (size_t)yb * BATCH + b0;
    #pragma unroll
    for (int i = 0; i < 4; ++i) {
        const int r = row0 + crow + i;
        if (r >= Cout) continue;
        const float s = bng[r] * rsqrtf(bnv[r] + 1e-5f);
        const float alpha = s;
        const float beta  = (bnb[r] - bnm[r]) * s + bnbe[r];
        float* Cr = Cb + (size_t)r * rowStride;
        float4 v0, v1;
        v0.x = fmaxf(acc[i][0] * alpha + beta, 0.f);
        v0.y = fmaxf(acc[i][1] * alpha + beta, 0.f);
        v0.z = fmaxf(acc[i][2] * alpha + beta, 0.f);
        v0.w = fmaxf(acc[i][3] * alpha + beta, 0.f);
        v1.x = fmaxf(acc[i][4] * alpha + beta, 0.f);
        v1.y = fmaxf(acc[i][5] * alpha + beta, 0.f);
        v1.z = fmaxf(acc[i][6] * alpha + beta, 0.f);
        v1.w = fmaxf(acc[i][7] * alpha + beta, 0.f);
        *(float4*)(Cr + c0)      = v0;
        *(float4*)(Cr + 64 + c0) = v1;
    }
}

__global__ void pool_kernel(const float* __restrict__ In, float* __restrict__ Out,
                            int C, int Hi, int Wi, int Ho, int Wo)
{
    const size_t total = (size_t)C * Ho * Wo * BATCH;
    size_t idx = (size_t)blockIdx.x * blockDim.x + threadIdx.x;
    if (idx >= total) return;
    const int b = idx & (BATCH - 1);
    size_t t = idx >> 13;
    const int ox = t % Wo; t /= Wo;
    const int oy = t % Ho; const int c = (int)(t / Ho);
    float mx = __int_as_float(0xff800000);
    #pragma unroll
    for (int ky = 0; ky < 3; ++ky) {
        const int iy = 2 * oy - 1 + ky;
        if ((unsigned)iy >= (unsigned)Hi) continue;
        #pragma unroll
        for (int kx = 0; kx < 3; ++kx) {
            const int ix = 2 * ox - 1 + kx;
            if ((unsigned)ix >= (unsigned)Wi) continue;
            mx = fmaxf(mx, In[(size_t)((c * Hi + iy) * Wi + ix) * BATCH + b]);
        }
    }
    Out[idx] = mx;
}

template<int STAGE>
__global__ void __launch_bounds__(256)
head_kernel(const float* __restrict__ Fin, const float* __restrict__ Gin,
            const float* __restrict__ Wb, const float* __restrict__ bb,
            float* __restrict__ out)
{
    __shared__ float Wbs[6000];
    __shared__ float bbs[10];
    const int n = blockIdx.y;
    const int b = blockIdx.x * 256 + threadIdx.x;
    const float* Wbn = Wb + (size_t)n * 6000;
    for (int i = threadIdx.x; i < 6000; i += 256) Wbs[i] = Wbn[i];
    if (threadIdx.x < 10) bbs[threadIdx.x] = bb[n * 10 + threadIdx.x];
    __syncthreads();

    float acc[10];
    #pragma unroll
    for (int c = 0; c < 10; ++c) acc[c] = bbs[c];

    const float* Fp = Fin + (size_t)n * 600 * BATCH + b;
    const float* Gp = (STAGE == 2) ? (Gin + (size_t)n * 600 * BATCH + b) : nullptr;
    for (int h = 0; h < 600; ++h) {
        float v = Fp[(size_t)h * BATCH];
        if (STAGE == 2) v += Gp[(size_t)h * BATCH];
        v = tanhf(v);
        #pragma unroll
        for (int c = 0; c < 10; ++c) acc[c] = fmaf(v, Wbs[h * 10 + c], acc[c]);
    }
    float mx = acc[0];
    #pragma unroll
    for (int c = 1; c < 10; ++c) mx = fmaxf(mx, acc[c]);
    float s = 0.f;
    #pragma unroll
    for (int c = 0; c < 10; ++c) { acc[c] = expf(acc[c] - mx); s += acc[c]; }
    const float inv = 1.f / s;
    if (STAGE == 1) {
        #pragma unroll
        for (int c = 0; c < 10; ++c) out[(size_t)(n * 10 + c) * BATCH + b] = acc[c] * inv;
    } else {
        #pragma unroll
        for (int c = 0; c < 10; ++c) out[((size_t)n * BATCH + b) * 10 + c] = acc[c] * inv;
    }
}

__global__ void mean_kernel(const float* __restrict__ second, float* __restrict__ mout) {
    const int idx = blockIdx.x * 256 + threadIdx.x;
    if (idx >= BATCH * 10) return;
    float s = 0.f;
    #pragma unroll
    for (int n = 0; n < NNODES; ++n) s += second[(size_t)n * BATCH * 10 + idx];
    mout[idx] = s * (1.f / 25.f);
}

// ---------------- launch ----------------------------------------------------
extern "C" void kernel_launch(void* const* d_in, const int* in_sizes, int n_in,
                              void* d_out, int out_size)
{
    const float* x  = (const float*)d_in[0];
    const float* W1 = (const float*)d_in[1];
    const float* b1 = (const float*)d_in[2];
    const float* g1 = (const float*)d_in[3];
    const float* be1= (const float*)d_in[4];
    const float* m1 = (const float*)d_in[5];
    const float* v1 = (const float*)d_in[6];
    const float* W2 = (const float*)d_in[7];
    const float* b2 = (const float*)d_in[8];
    const float* g2 = (const float*)d_in[9];
    const float* be2= (const float*)d_in[10];
    const float* m2 = (const float*)d_in[11];
    const float* v2 = (const float*)d_in[12];
    const float* W3 = (const float*)d_in[13];
    const float* b3 = (const float*)d_in[14];
    const float* g3 = (const float*)d_in[15];
    const float* be3= (const float*)d_in[16];
    const float* m3 = (const float*)d_in[17];
    const float* v3 = (const float*)d_in[18];
    const float* W4 = (const float*)d_in[19];
    const float* b4 = (const float*)d_in[20];
    const float* g4 = (const float*)d_in[21];
    const float* be4= (const float*)d_in[22];
    const float* m4 = (const float*)d_in[23];
    const float* v4 = (const float*)d_in[24];
    const float* Wa = (const float*)d_in[25];
    const float* ba = (const float*)d_in[26];
    const float* Wb = (const float*)d_in[27];
    const float* bb = (const float*)d_in[28];

    float *Xt, *C1, *P1, *C2, *P2, *C3, *C4, *F, *G, *PR;
    cudaGetSymbolAddress((void**)&Xt, g_Xt);
    cudaGetSymbolAddress((void**)&C1, g_C1);
    cudaGetSymbolAddress((void**)&P1, g_P1);
    cudaGetSymbolAddress((void**)&C2, g_C2);
    cudaGetSymbolAddress((void**)&P2, g_P2);
    cudaGetSymbolAddress((void**)&C3, g_C3);
    cudaGetSymbolAddress((void**)&C4, g_C4);
    cudaGetSymbolAddress((void**)&F,  g_F);
    cudaGetSymbolAddress((void**)&G,  g_G);
    cudaGetSymbolAddress((void**)&PR, g_PR);

    float* out = (float*)d_out;
    float* second = out + BATCH * 10;

    nei_init_kernel<<<1, 32>>>();
    transpose_kernel<<<dim3(38, 256), dim3(32, 8)>>>(x);

    // conv1 (3->64, 20x20)  SIMT
    gemm_kernel<<<dim3(64, 400, 1), 256>>>(W1, Xt, C1, 27, 64, 20, 20,
                                           b1, g1, be1, m1, v1);
    pool_kernel<<<(int)(((size_t)64 * 100 * BATCH + 255) / 256), 256>>>(C1, P1, 64, 20, 20, 10, 10);

    // conv2 (64->128, 10x10)  mma.sync
    mma_gemm<0><<<dim3(100, 128, 1), 256>>>(W2, P1, C2, 576, 128, 10, 10,
                                            b2, g2, be2, m2, v2, nullptr);
    pool_kernel<<<(int)(((size_t)128 * 25 * BATCH + 255) / 256), 256>>>(C2, P2, 128, 10, 10, 5, 5);

    // conv3 (128->256, 5x5)
    mma_gemm<0><<<dim3(25, 128, 2), 256>>>(W3, P2, C3, 1152, 256, 5, 5,
                                           b3, g3, be3, m3, v3, nullptr);
    // conv4 (256->256, 5x5)
    mma_gemm<0><<<dim3(25, 128, 2), 256>>>(W4, C3, C4, 2304, 256, 5, 5,
                                           b4, g4, be4, m4, v4, nullptr);

    // F[n] = Wa[n][80:336].T @ feats[n] + ba[n]
    mma_gemm<1><<<dim3(25, 128, 5), 256>>>(Wa, C4, F, 256, 600, 0, 0,
                                           nullptr, nullptr, nullptr, nullptr, nullptr, ba);
    // stage 1 predictions
    head_kernel<1><<<dim3(32, 25), 256>>>(F, nullptr, Wb, bb, PR);
    // G[n] = Wa[n][0:80].T @ neighbor-preds[n]
    mma_gemm<2><<<dim3(25, 128, 5), 256>>>(Wa, PR, G, 80, 600, 0, 0,
                                           nullptr, nullptr, nullptr, nullptr, nullptr, nullptr);
    // stage 2 -> second [25][B][10]
    head_kernel<2><<<dim3(32, 25), 256>>>(F, G, Wb, bb, second);
    // mean over nodes
    mean_kernel<<<(BATCH * 10 + 255) / 256, 256>>>(second, out);
}

// round 6
// speedup vs baseline: 2.2075x; 1.0262x over previous
#include <cuda_runtime.h>
#include <cuda_bf16.h>
#include <cstdint>
#include <cstddef>

#define BATCH 8192
#define NNODES 25
typedef __nv_bfloat16 bf16;

// ---------------- scratch (device globals; no allocations allowed) ---------
__device__ float g_C1[(size_t)64  * 400 * BATCH];     // conv1 out fp32
__device__ float g_C2[(size_t)128 * 100 * BATCH];     // conv2 out fp32
__device__ float g_F [(size_t)NNODES * 600 * BATCH];
__device__ float g_G [(size_t)NNODES * 600 * BATCH];
__device__ int   g_NEI[NNODES * 8];

// bf16 hi/lo operand buffers
__device__ bf16 g_Xth[(size_t)1200 * BATCH],      g_Xtl[(size_t)1200 * BATCH];
__device__ bf16 g_P1h[(size_t)64 * 100 * BATCH],  g_P1l[(size_t)64 * 100 * BATCH];
__device__ bf16 g_P2h[(size_t)128 * 25 * BATCH],  g_P2l[(size_t)128 * 25 * BATCH];
__device__ bf16 g_C3h[(size_t)256 * 25 * BATCH],  g_C3l[(size_t)256 * 25 * BATCH];
__device__ bf16 g_C4h[(size_t)256 * 25 * BATCH],  g_C4l[(size_t)256 * 25 * BATCH];
__device__ bf16 g_PRh[(size_t)NNODES * 10 * BATCH], g_PRl[(size_t)NNODES * 10 * BATCH];
__device__ bf16 g_W1h[64 * 32],    g_W1l[64 * 32];
__device__ bf16 g_W2h[128 * 576],  g_W2l[128 * 576];
__device__ bf16 g_W3h[256 * 1152], g_W3l[256 * 1152];
__device__ bf16 g_W4h[256 * 2304], g_W4l[256 * 2304];
__device__ bf16 g_Wath[(size_t)NNODES * 600 * 336], g_Watl[(size_t)NNODES * 600 * 336];

// ======================= helpers ===========================================
__device__ __forceinline__ uint32_t s2u(const void* p) {
    uint32_t a;
    asm("{ .reg .u64 t; cvta.to.shared.u64 t, %1; cvt.u32.u64 %0, t; }"
        : "=r"(a) : "l"(p));
    return a;
}
__device__ __forceinline__ void ldsm4(uint32_t* r, uint32_t addr) {
    asm volatile("ldmatrix.sync.aligned.m8n8.x4.shared.b16 {%0,%1,%2,%3}, [%4];"
        : "=r"(r[0]), "=r"(r[1]), "=r"(r[2]), "=r"(r[3]) : "r"(addr));
}
__device__ __forceinline__ void ldsm4t(uint32_t* r, uint32_t addr) {
    asm volatile("ldmatrix.sync.aligned.m8n8.x4.trans.shared.b16 {%0,%1,%2,%3}, [%4];"
        : "=r"(r[0]), "=r"(r[1]), "=r"(r[2]), "=r"(r[3]) : "r"(addr));
}
__device__ __forceinline__ void mma16816(float* c, const uint32_t* a, const uint32_t* b) {
    asm volatile("mma.sync.aligned.m16n8k16.row.col.f32.bf16.bf16.f32 "
        "{%0,%1,%2,%3}, {%4,%5,%6,%7}, {%8,%9}, {%0,%1,%2,%3};"
        : "+f"(c[0]), "+f"(c[1]), "+f"(c[2]), "+f"(c[3])
        : "r"(a[0]), "r"(a[1]), "r"(a[2]), "r"(a[3]), "r"(b[0]), "r"(b[1]));
}
__device__ __forceinline__ uint32_t pack_bf2(float a, float b) {
    __nv_bfloat162 t = __floats2bfloat162_rn(a, b);
    return *reinterpret_cast<uint32_t*>(&t);
}
__device__ __forceinline__ void split4(float4 v, uint2& hv, uint2& lv) {
    bf16 h0 = __float2bfloat16(v.x), h1 = __float2bfloat16(v.y);
    bf16 h2 = __float2bfloat16(v.z), h3 = __float2bfloat16(v.w);
    float l0 = v.x - __bfloat162float(h0), l1 = v.y - __bfloat162float(h1);
    float l2 = v.z - __bfloat162float(h2), l3 = v.w - __bfloat162float(h3);
    __nv_bfloat162 p0 = __halves2bfloat162(h0, h1);
    __nv_bfloat162 p1 = __halves2bfloat162(h2, h3);
    hv = make_uint2(*reinterpret_cast<uint32_t*>(&p0), *reinterpret_cast<uint32_t*>(&p1));
    lv = make_uint2(pack_bf2(l0, l1), pack_bf2(l2, l3));
}
__device__ __forceinline__ float fast_tanh(float v) {
    v = fminf(fmaxf(v, -15.f), 15.f);
    const float t = __expf(2.f * v);
    return __fdividef(t - 1.f, t + 1.f);
}

// ======================= operand split kernels =============================
__global__ void split_plain(const float* __restrict__ src, bf16* __restrict__ h,
                            bf16* __restrict__ l, int n) {
    const int i = blockIdx.x * 256 + threadIdx.x;
    if (i >= n) return;
    const float v = src[i];
    const bf16 hb = __float2bfloat16(v);
    h[i] = hb;
    l[i] = __float2bfloat16(v - __bfloat162float(hb));
}
__global__ void split_w1(const float* __restrict__ W1) {   // [64][27] -> [64][32] pad
    const int i = blockIdx.x * 256 + threadIdx.x;
    if (i >= 64 * 32) return;
    const int r = i >> 5, k = i & 31;
    const float v = (k < 27) ? W1[r * 27 + k] : 0.f;
    const bf16 hb = __float2bfloat16(v);
    g_W1h[i] = hb;
    g_W1l[i] = __float2bfloat16(v - __bfloat162float(hb));
}
__global__ void split_wat(const float* __restrict__ Wa) {  // [n][336][600] -> [n][600][336]
    __shared__ float t[32][33];
    const int n = blockIdx.z;
    const int i0 = blockIdx.x * 32, h0 = blockIdx.y * 32;
    const int tx = threadIdx.x, ty = threadIdx.y;
    const float* W = Wa + (size_t)n * 336 * 600;
    #pragma unroll
    for (int j = 0; j < 32; j += 8) {
        const int i2 = i0 + ty + j, hh = h0 + tx;
        t[ty + j][tx] = (i2 < 336 && hh < 600) ? W[i2 * 600 + hh] : 0.f;
    }
    __syncthreads();
    bf16* Hh = g_Wath + (size_t)n * 600 * 336;
    bf16* Hl = g_Watl + (size_t)n * 600 * 336;
    #pragma unroll
    for (int j = 0; j < 32; j += 8) {
        const int hh = h0 + ty + j, i2 = i0 + tx;
        if (hh < 600 && i2 < 336) {
            const float v = t[tx][ty + j];
            const bf16 hb = __float2bfloat16(v);
            Hh[hh * 336 + i2] = hb;
            Hl[hh * 336 + i2] = __float2bfloat16(v - __bfloat162float(hb));
        }
    }
}

// ---------------- NCHW -> [p][b] transpose + split -------------------------
__global__ void transpose_kernel(const float* __restrict__ x) {
    __shared__ float tile[32][33];
    const int p0 = blockIdx.x * 32;
    const int b0 = blockIdx.y * 32;
    const int tx = threadIdx.x, ty = threadIdx.y;
    #pragma unroll
    for (int i = 0; i < 32; i += 8) {
        int p = p0 + tx, b = b0 + ty + i;
        if (p < 1200) tile[ty + i][tx] = x[(size_t)b * 1200 + p];
    }
    __syncthreads();
    #pragma unroll
    for (int i = 0; i < 32; i += 8) {
        int p = p0 + ty + i, b = b0 + tx;
        if (p < 1200) {
            const float v = tile[tx][ty + i];
            const bf16 hb = __float2bfloat16(v);
            g_Xth[(size_t)p * BATCH + b] = hb;
            g_Xtl[(size_t)p * BATCH + b] = __float2bfloat16(v - __bfloat162float(hb));
        }
    }
}

// ======================= mma.sync split-bf16 GEMM ==========================
// Tile M=128 x N=64(batch) x K=32.  8 warps (4m x 2n), warp 32x32.
// MODE 0: conv im2col, BN+ReLU epi.  MODE 1: F GEMM (+bias).  MODE 2: G GEMM.
// OUTBF: 1 -> write bf16 hi/lo pair instead of fp32.
constexpr int ASTR = 40;
constexpr int BSTR = 72;

template<int MODE, int OUTBF>
__global__ void __launch_bounds__(256, 2)
mma_gemm(const bf16* __restrict__ Ah, const bf16* __restrict__ Al,
         const bf16* __restrict__ Bh, const bf16* __restrict__ Bl,
         float* __restrict__ Cf, bf16* __restrict__ Ch, bf16* __restrict__ Cl,
         int K, int Kvalid, int Cout, int H, int W, int astr,
         const float* __restrict__ bnb, const float* __restrict__ bng,
         const float* __restrict__ bnbe, const float* __restrict__ bnm,
         const float* __restrict__ bnv, const float* __restrict__ bias)
{
    __shared__ __align__(16) bf16 sAh[128 * ASTR], sAl[128 * ASTR];
    __shared__ __align__(16) bf16 sBh[32 * BSTR],  sBl[32 * BSTR];

    const int tid = threadIdx.x, wid = tid >> 5, lid = tid & 31;
    const int yb   = blockIdx.x;
    const int bofs = blockIdx.y * 64;
    const int row0 = blockIdx.z * 128;
    const int wm = wid >> 1, wn = wid & 1;

    int oy = 0, ox = 0;
    if (MODE == 0) { oy = yb / W; ox = yb - oy * W; }
    const bf16* Abh = Ah;
    const bf16* Abl = Al;
    if (MODE == 1) { Abh += (size_t)yb * 600 * 336 + 80; Abl += (size_t)yb * 600 * 336 + 80; }
    if (MODE == 2) { Abh += (size_t)yb * 600 * 336;      Abl += (size_t)yb * 600 * 336; }

    const uint32_t uAh = s2u(sAh), uAl = s2u(sAl);
    const uint32_t uBh = s2u(sBh), uBl = s2u(sBl);

    float acc[2][4][4];
    #pragma unroll
    for (int a = 0; a < 2; ++a)
        #pragma unroll
        for (int b = 0; b < 4; ++b)
            #pragma unroll
            for (int c = 0; c < 4; ++c) acc[a][b][c] = 0.f;

    const int nch = K / 32;
    for (int kc = 0; kc < nch; ++kc) {
        const int k0 = kc * 32;
        __syncthreads();

        // ---- A producer: pure bf16 copy ----
        {
            const int r  = tid >> 1;
            const int kk = (tid & 1) * 16;
            const int rg = row0 + r;
            uint4 h0 = make_uint4(0, 0, 0, 0), h1 = h0, l0 = h0, l1 = h0;
            if (rg < Cout) {
                const bf16* ph = Abh + (size_t)rg * astr + k0 + kk;
                const bf16* pl = Abl + (size_t)rg * astr + k0 + kk;
                h0 = *(const uint4*)ph;       h1 = *(const uint4*)(ph + 8);
                l0 = *(const uint4*)pl;       l1 = *(const uint4*)(pl + 8);
            }
            *(uint4*)&sAh[r * ASTR + kk]     = h0;
            *(uint4*)&sAh[r * ASTR + kk + 8] = h1;
            *(uint4*)&sAl[r * ASTR + kk]     = l0;
            *(uint4*)&sAl[r * ASTR + kk + 8] = l1;
        }

        // ---- B producer: pure bf16 copy w/ gather ----
        {
            const int k   = tid >> 3;
            const int seg = (tid & 7) * 8;
            const int kk  = k0 + k;
            uint4 hv = make_uint4(0, 0, 0, 0), lv = hv;
            bool ok = false;
            size_t rowoff = 0;
            if (MODE == 0) {
                if (kk < Kvalid) {
                    const int ci = kk / 9, r9 = kk - ci * 9;
                    const int ky = r9 / 3, kx = r9 - ky * 3;
                    const int iy = oy + ky - 1, ix = ox + kx - 1;
                    if ((unsigned)iy < (unsigned)H && (unsigned)ix < (unsigned)W) {
                        ok = true;
                        rowoff = (size_t)((ci * H + iy) * W + ix) * BATCH;
                    }
                }
            } else if (MODE == 1) {
                ok = true;
                rowoff = ((size_t)kk * NNODES + yb) * BATCH;
            } else {
                if (kk < Kvalid) {
                    const int slot = kk / 10, cc = kk - slot * 10;
                    const int mn = g_NEI[yb * 8 + slot];
                    if (mn >= 0) { ok = true; rowoff = (size_t)(mn * 10 + cc) * BATCH; }
                }
            }
            if (ok) {
                hv = *(const uint4*)(Bh + rowoff + bofs + seg);
                lv = *(const uint4*)(Bl + rowoff + bofs + seg);
            }
            *(uint4*)&sBh[k * BSTR + seg] = hv;
            *(uint4*)&sBl[k * BSTR + seg] = lv;
        }

        __syncthreads();

        // ---- compute: 2 k16 steps, 3 split passes ----
        #pragma unroll
        for (int ks = 0; ks < 2; ++ks) {
            uint32_t ah[2][4], al[2][4], bh[2][4], bl[2][4];
            #pragma unroll
            for (int mt = 0; mt < 2; ++mt) {
                const uint32_t off = (uint32_t)(wm * 32 + mt * 16 + (lid & 15)) * (ASTR * 2)
                                   + ks * 32 + (lid >> 4) * 16;
                ldsm4(ah[mt], uAh + off);
                ldsm4(al[mt], uAl + off);
            }
            #pragma unroll
            for (int ng = 0; ng < 2; ++ng) {
                const uint32_t off = (uint32_t)(ks * 16 + (lid & 15)) * (BSTR * 2)
                                   + (wn * 32 + ng * 16) * 2 + (lid >> 4) * 16;
                ldsm4t(bh[ng], uBh + off);
                ldsm4t(bl[ng], uBl + off);
            }
            #pragma unroll
            for (int mt = 0; mt < 2; ++mt) {
                #pragma unroll
                for (int nt = 0; nt < 4; ++nt) {
                    const int ng = nt >> 1, p = (nt & 1) * 2;
                    mma16816(acc[mt][nt], ah[mt], &bh[ng][p]);
                    mma16816(acc[mt][nt], ah[mt], &bl[ng][p]);
                    mma16816(acc[mt][nt], al[mt], &bh[ng][p]);
                }
            }
        }
    }

    // ---------------- epilogue ----------------
    const int g  = lid >> 2;
    const int qc = (lid & 3) * 2;
    #pragma unroll
    for (int mt = 0; mt < 2; ++mt) {
        const int r0g = row0 + wm * 32 + mt * 16 + g;
        const int r1g = r0g + 8;
        const bool ok0 = r0g < Cout, ok1 = r1g < Cout;
        float al0 = 1.f, be0 = 0.f, al1 = 1.f, be1 = 0.f;
        if (MODE == 0) {
            if (ok0) {
                const float s0 = bng[r0g] * rsqrtf(bnv[r0g] + 1e-5f);
                al0 = s0; be0 = (bnb[r0g] - bnm[r0g]) * s0 + bnbe[r0g];
            }
            if (ok1) {
                const float s1 = bng[r1g] * rsqrtf(bnv[r1g] + 1e-5f);
                al1 = s1; be1 = (bnb[r1g] - bnm[r1g]) * s1 + bnbe[r1g];
            }
        } else if (MODE == 1) {
            if (ok0) be0 = bias[yb * 600 + r0g];
            if (ok1) be1 = bias[yb * 600 + r1g];
        }
        size_t off0, off1;
        if (MODE == 0) {
            off0 = ((size_t)r0g * H * W + yb) * BATCH + bofs;
            off1 = ((size_t)r1g * H * W + yb) * BATCH + bofs;
        } else {
            off0 = ((size_t)yb * 600 + r0g) * BATCH + bofs;
            off1 = ((size_t)yb * 600 + r1g) * BATCH + bofs;
        }
        #pragma unroll
        for (int nt = 0; nt < 4; ++nt) {
            const int col = wn * 32 + nt * 8 + qc;
            float2 v0, v1;
            v0.x = acc[mt][nt][0] * al0 + be0;  v0.y = acc[mt][nt][1] * al0 + be0;
            v1.x = acc[mt][nt][2] * al1 + be1;  v1.y = acc[mt][nt][3] * al1 + be1;
            if (MODE == 0) {
                v0.x = fmaxf(v0.x, 0.f); v0.y = fmaxf(v0.y, 0.f);
                v1.x = fmaxf(v1.x, 0.f); v1.y = fmaxf(v1.y, 0.f);
            }
            if (OUTBF) {
                if (ok0) {
                    const bf16 h0 = __float2bfloat16(v0.x), h1 = __float2bfloat16(v0.y);
                    __nv_bfloat162 hp = __halves2bfloat162(h0, h1);
                    *(uint32_t*)&Ch[off0 + col] = *reinterpret_cast<uint32_t*>(&hp);
                    *(uint32_t*)&Cl[off0 + col] =
                        pack_bf2(v0.x - __bfloat162float(h0), v0.y - __bfloat162float(h1));
                }
                if (ok1) {
                    const bf16 h0 = __float2bfloat16(v1.x), h1 = __float2bfloat16(v1.y);
                    __nv_bfloat162 hp = __halves2bfloat162(h0, h1);
                    *(uint32_t*)&Ch[off1 + col] = *reinterpret_cast<uint32_t*>(&hp);
                    *(uint32_t*)&Cl[off1 + col] =
                        pack_bf2(v1.x - __bfloat162float(h0), v1.y - __bfloat162float(h1));
                }
            } else {
                if (ok0) *(float2*)(Cf + off0 + col) = v0;
                if (ok1) *(float2*)(Cf + off1 + col) = v1;
            }
        }
    }
}

// ======================= SIMT kernels ======================================
__global__ void nei_init_kernel() {
    int i = threadIdx.x;
    if (i >= NNODES) return;
    const int w = 5, size = 25;
    int n[8]; int cnt = 0;
    if (i - w >= 0)                               n[cnt++] = i - w;
    if (i % w != 0)                               n[cnt++] = i - 1;
    if ((i + 1) % w != 0)                         n[cnt++] = i + 1;
    if (i + w < size)                             n[cnt++] = i + w;
    if (i - w - 1 >= 0 && i % w != 0)             n[cnt++] = i - w - 1;
    if (i - w + 1 >= 0 && (i + 1) % w != 0)       n[cnt++] = i - w + 1;
    if (i + w - 1 < size && i % w != 0)           n[cnt++] = i + w - 1;
    if (i + w + 1 < size && (i + 1) % w != 0)     n[cnt++] = i + w + 1;
    while (cnt < 8) n[cnt++] = -1;
    for (int j = 0; j < 8; ++j) g_NEI[i * 8 + j] = n[j];
}

// vectorized maxpool 3x3 s2 p1, fp32 in -> bf16 hi/lo out
__global__ void poolv_kernel(const float* __restrict__ In,
                             bf16* __restrict__ Oh, bf16* __restrict__ Ol,
                             int C, int Hi, int Wi, int Ho, int Wo)
{
    const size_t total = (size_t)C * Ho * Wo * (BATCH / 4);
    const size_t idx = (size_t)blockIdx.x * blockDim.x + threadIdx.x;
    if (idx >= total) return;
    const int b4 = (int)(idx & (BATCH / 4 - 1));
    size_t t = idx >> 11;                      // BATCH/4 = 2048 = 2^11
    const int ox = (int)(t % Wo); t /= Wo;
    const int oy = (int)(t % Ho); const int c = (int)(t / Ho);
    const float ninf = __int_as_float(0xff800000);
    float4 mx = make_float4(ninf, ninf, ninf, ninf);
    #pragma unroll
    for (int ky = 0; ky < 3; ++ky) {
        const int iy = 2 * oy - 1 + ky;
        if ((unsigned)iy >= (unsigned)Hi) continue;
        #pragma unroll
        for (int kx = 0; kx < 3; ++kx) {
            const int ix = 2 * ox - 1 + kx;
            if ((unsigned)ix >= (unsigned)Wi) continue;
            const float4 v = *(const float4*)(In + (size_t)((c * Hi + iy) * Wi + ix) * BATCH + b4 * 4);
            mx.x = fmaxf(mx.x, v.x); mx.y = fmaxf(mx.y, v.y);
            mx.z = fmaxf(mx.z, v.z); mx.w = fmaxf(mx.w, v.w);
        }
    }
    uint2 hv, lv;
    split4(mx, hv, lv);
    const size_t off = (size_t)((c * Ho + oy) * Wo + ox) * BATCH + b4 * 4;
    *(uint2*)&Oh[off] = hv;
    *(uint2*)&Ol[off] = lv;
}

// MLP head: tanh + Wb + softmax.  STAGE 1 -> bf16 hi/lo preds; STAGE 2 -> fp32 out.
template<int STAGE>
__global__ void __launch_bounds__(256)
head_kernel(const float* __restrict__ Fin, const float* __restrict__ Gin,
            const float* __restrict__ Wb, const float* __restrict__ bb,
            float* __restrict__ out)
{
    __shared__ float Wbs[6000];
    __shared__ float bbs[10];
    const int n = blockIdx.y;
    const int b = blockIdx.x * 256 + threadIdx.x;
    const float* Wbn = Wb + (size_t)n * 6000;
    for (int i = threadIdx.x; i < 6000; i += 256) Wbs[i] = Wbn[i];
    if (threadIdx.x < 10) bbs[threadIdx.x] = bb[n * 10 + threadIdx.x];
    __syncthreads();

    float acc[10];
    #pragma unroll
    for (int c = 0; c < 10; ++c) acc[c] = bbs[c];

    const float* Fp = Fin + (size_t)n * 600 * BATCH + b;
    const float* Gp = (STAGE == 2) ? (Gin + (size_t)n * 600 * BATCH + b) : nullptr;
    for (int h = 0; h < 600; ++h) {
        float v = Fp[(size_t)h * BATCH];
        if (STAGE == 2) v += Gp[(size_t)h * BATCH];
        v = fast_tanh(v);
        #pragma unroll
        for (int c = 0; c < 10; ++c) acc[c] = fmaf(v, Wbs[h * 10 + c], acc[c]);
    }
    float mx = acc[0];
    #pragma unroll
    for (int c = 1; c < 10; ++c) mx = fmaxf(mx, acc[c]);
    float s = 0.f;
    #pragma unroll
    for (int c = 0; c < 10; ++c) { acc[c] = expf(acc[c] - mx); s += acc[c]; }
    const float inv = 1.f / s;
    if (STAGE == 1) {
        #pragma unroll
        for (int c = 0; c < 10; ++c) {
            const float p = acc[c] * inv;
            const bf16 hb = __float2bfloat16(p);
            g_PRh[(size_t)(n * 10 + c) * BATCH + b] = hb;
            g_PRl[(size_t)(n * 10 + c) * BATCH + b] =
                __float2bfloat16(p - __bfloat162float(hb));
        }
    } else {
        #pragma unroll
        for (int c = 0; c < 10; ++c) out[((size_t)n * BATCH + b) * 10 + c] = acc[c] * inv;
    }
}

__global__ void mean_kernel(const float* __restrict__ second, float* __restrict__ mout) {
    const int idx = blockIdx.x * 256 + threadIdx.x;
    if (idx >= BATCH * 10) return;
    float s = 0.f;
    #pragma unroll
    for (int n = 0; n < NNODES; ++n) s += second[(size_t)n * BATCH * 10 + idx];
    mout[idx] = s * (1.f / 25.f);
}

// ---------------- launch ----------------------------------------------------
extern "C" void kernel_launch(void* const* d_in, const int* in_sizes, int n_in,
                              void* d_out, int out_size)
{
    const float* x  = (const float*)d_in[0];
    const float* W1 = (const float*)d_in[1];
    const float* b1 = (const float*)d_in[2];
    const float* g1 = (const float*)d_in[3];
    const float* be1= (const float*)d_in[4];
    const float* m1 = (const float*)d_in[5];
    const float* v1 = (const float*)d_in[6];
    const float* W2 = (const float*)d_in[7];
    const float* b2 = (const float*)d_in[8];
    const float* g2 = (const float*)d_in[9];
    const float* be2= (const float*)d_in[10];
    const float* m2 = (const float*)d_in[11];
    const float* v2 = (const float*)d_in[12];
    const float* W3 = (const float*)d_in[13];
    const float* b3 = (const float*)d_in[14];
    const float* g3 = (const float*)d_in[15];
    const float* be3= (const float*)d_in[16];
    const float* m3 = (const float*)d_in[17];
    const float* v3 = (const float*)d_in[18];
    const float* W4 = (const float*)d_in[19];
    const float* b4 = (const float*)d_in[20];
    const float* g4 = (const float*)d_in[21];
    const float* be4= (const float*)d_in[22];
    const float* m4 = (const float*)d_in[23];
    const float* v4 = (const float*)d_in[24];
    const float* Wa = (const float*)d_in[25];
    const float* ba = (const float*)d_in[26];
    const float* Wb = (const float*)d_in[27];
    const float* bb = (const float*)d_in[28];

    float *C1, *C2, *F, *G;
    cudaGetSymbolAddress((void**)&C1, g_C1);
    cudaGetSymbolAddress((void**)&C2, g_C2);
    cudaGetSymbolAddress((void**)&F,  g_F);
    cudaGetSymbolAddress((void**)&G,  g_G);
    bf16 *Xth, *Xtl, *P1h, *P1l, *P2h, *P2l, *C3h, *C3l, *C4h, *C4l, *PRh, *PRl;
    bf16 *W1h, *W1l, *W2h, *W2l, *W3h, *W3l, *W4h, *W4l, *Wath, *Watl;
    cudaGetSymbolAddress((void**)&Xth, g_Xth);  cudaGetSymbolAddress((void**)&Xtl, g_Xtl);
    cudaGetSymbolAddress((void**)&P1h, g_P1h);  cudaGetSymbolAddress((void**)&P1l, g_P1l);
    cudaGetSymbolAddress((void**)&P2h, g_P2h);  cudaGetSymbolAddress((void**)&P2l, g_P2l);
    cudaGetSymbolAddress((void**)&C3h, g_C3h);  cudaGetSymbolAddress((void**)&C3l, g_C3l);
    cudaGetSymbolAddress((void**)&C4h, g_C4h);  cudaGetSymbolAddress((void**)&C4l, g_C4l);
    cudaGetSymbolAddress((void**)&PRh, g_PRh);  cudaGetSymbolAddress((void**)&PRl, g_PRl);
    cudaGetSymbolAddress((void**)&W1h, g_W1h);  cudaGetSymbolAddress((void**)&W1l, g_W1l);
    cudaGetSymbolAddress((void**)&W2h, g_W2h);  cudaGetSymbolAddress((void**)&W2l, g_W2l);
    cudaGetSymbolAddress((void**)&W3h, g_W3h);  cudaGetSymbolAddress((void**)&W3l, g_W3l);
    cudaGetSymbolAddress((void**)&W4h, g_W4h);  cudaGetSymbolAddress((void**)&W4l, g_W4l);
    cudaGetSymbolAddress((void**)&Wath, g_Wath); cudaGetSymbolAddress((void**)&Watl, g_Watl);

    float* out = (float*)d_out;
    float* second = out + BATCH * 10;

    nei_init_kernel<<<1, 32>>>();
    // operand preparation
    transpose_kernel<<<dim3(38, 256), dim3(32, 8)>>>(x);
    split_w1<<<8, 256>>>(W1);
    split_plain<<<(128 * 576 + 255) / 256, 256>>>(W2, W2h, W2l, 128 * 576);
    split_plain<<<(256 * 1152 + 255) / 256, 256>>>(W3, W3h, W3l, 256 * 1152);
    split_plain<<<(256 * 2304 + 255) / 256, 256>>>(W4, W4h, W4l, 256 * 2304);
    split_wat<<<dim3(11, 19, 25), dim3(32, 8)>>>(Wa);

    // conv1 (3->64, 20x20): K pad 27->32
    mma_gemm<0, 0><<<dim3(400, 128, 1), 256>>>(W1h, W1l, Xth, Xtl, C1, nullptr, nullptr,
                                               32, 27, 64, 20, 20, 32,
                                               b1, g1, be1, m1, v1, nullptr);
    poolv_kernel<<<(int)(((size_t)64 * 100 * (BATCH / 4) + 255) / 256), 256>>>(
        C1, P1h, P1l, 64, 20, 20, 10, 10);

    // conv2 (64->128, 10x10)
    mma_gemm<0, 0><<<dim3(100, 128, 1), 256>>>(W2h, W2l, P1h, P1l, C2, nullptr, nullptr,
                                               576, 576, 128, 10, 10, 576,
                                               b2, g2, be2, m2, v2, nullptr);
    poolv_kernel<<<(int)(((size_t)128 * 25 * (BATCH / 4) + 255) / 256), 256>>>(
        C2, P2h, P2l, 128, 10, 10, 5, 5);

    // conv3 (128->256, 5x5) -> bf16 hi/lo
    mma_gemm<0, 1><<<dim3(25, 128, 2), 256>>>(W3h, W3l, P2h, P2l, nullptr, C3h, C3l,
                                              1152, 1152, 256, 5, 5, 1152,
                                              b3, g3, be3, m3, v3, nullptr);
    // conv4 (256->256, 5x5) -> bf16 hi/lo
    mma_gemm<0, 1><<<dim3(25, 128, 2), 256>>>(W4h, W4l, C3h, C3l, nullptr, C4h, C4l,
                                              2304, 2304, 256, 5, 5, 2304,
                                              b4, g4, be4, m4, v4, nullptr);

    // F[n] = Wa[n][80:336].T @ feats + ba -> fp32
    mma_gemm<1, 0><<<dim3(25, 128, 5), 256>>>(Wath, Watl, C4h, C4l, F, nullptr, nullptr,
                                              256, 256, 600, 0, 0, 336,
                                              nullptr, nullptr, nullptr, nullptr, nullptr, ba);
    // stage 1 predictions -> bf16 hi/lo
    head_kernel<1><<<dim3(32, 25), 256>>>(F, nullptr, Wb, bb, nullptr);
    // G[n] = Wa[n][0:80].T @ neighbor preds -> fp32
    mma_gemm<2, 0><<<dim3(25, 128, 5), 256>>>(Wath, Watl, PRh, PRl, G, nullptr, nullptr,
                                              96, 80, 600, 0, 0, 336,
                                              nullptr, nullptr, nullptr, nullptr, nullptr, nullptr);
    // stage 2 -> second [25][B][10]
    head_kernel<2><<<dim3(32, 25), 256>>>(F, G, Wb, bb, second);
    // mean over nodes
    mean_kernel<<<(BATCH * 10 + 255) / 256, 256>>>(second, out);
}

// round 7
// speedup vs baseline: 2.6551x; 1.2028x over previous
#include <cuda_runtime.h>
#include <cuda_bf16.h>
#include <cstdint>
#include <cstddef>

#define BATCH 8192
#define NNODES 25
typedef __nv_bfloat16 bf16;

// ---------------- scratch (device globals; no allocations allowed) ---------
__device__ float g_C1[(size_t)64  * 400 * BATCH];
__device__ float g_C2[(size_t)128 * 100 * BATCH];
__device__ float g_F [(size_t)NNODES * 600 * BATCH];
__device__ float g_G [(size_t)NNODES * 600 * BATCH];
__device__ int   g_NEI[NNODES * 8];

__device__ bf16 g_Xth[(size_t)1200 * BATCH],      g_Xtl[(size_t)1200 * BATCH];
__device__ bf16 g_P1h[(size_t)64 * 100 * BATCH],  g_P1l[(size_t)64 * 100 * BATCH];
__device__ bf16 g_P2h[(size_t)128 * 25 * BATCH],  g_P2l[(size_t)128 * 25 * BATCH];
__device__ bf16 g_C3h[(size_t)256 * 25 * BATCH],  g_C3l[(size_t)256 * 25 * BATCH];
__device__ bf16 g_C4h[(size_t)256 * 25 * BATCH],  g_C4l[(size_t)256 * 25 * BATCH];
__device__ bf16 g_PRh[(size_t)NNODES * 10 * BATCH], g_PRl[(size_t)NNODES * 10 * BATCH];
__device__ bf16 g_W1h[64 * 32],    g_W1l[64 * 32];
__device__ bf16 g_W2h[128 * 576],  g_W2l[128 * 576];
__device__ bf16 g_W3h[256 * 1152], g_W3l[256 * 1152];
__device__ bf16 g_W4h[256 * 2304], g_W4l[256 * 2304];
__device__ bf16 g_Wath[(size_t)NNODES * 600 * 336], g_Watl[(size_t)NNODES * 600 * 336];

// ======================= helpers ===========================================
__device__ __forceinline__ uint32_t s2u(const void* p) {
    uint32_t a;
    asm("{ .reg .u64 t; cvta.to.shared.u64 t, %1; cvt.u32.u64 %0, t; }"
        : "=r"(a) : "l"(p));
    return a;
}
__device__ __forceinline__ void ldsm4(uint32_t* r, uint32_t addr) {
    asm volatile("ldmatrix.sync.aligned.m8n8.x4.shared.b16 {%0,%1,%2,%3}, [%4];"
        : "=r"(r[0]), "=r"(r[1]), "=r"(r[2]), "=r"(r[3]) : "r"(addr));
}
__device__ __forceinline__ void ldsm4t(uint32_t* r, uint32_t addr) {
    asm volatile("ldmatrix.sync.aligned.m8n8.x4.trans.shared.b16 {%0,%1,%2,%3}, [%4];"
        : "=r"(r[0]), "=r"(r[1]), "=r"(r[2]), "=r"(r[3]) : "r"(addr));
}
__device__ __forceinline__ void mma16816(float* c, const uint32_t* a, const uint32_t* b) {
    asm volatile("mma.sync.aligned.m16n8k16.row.col.f32.bf16.bf16.f32 "
        "{%0,%1,%2,%3}, {%4,%5,%6,%7}, {%8,%9}, {%0,%1,%2,%3};"
        : "+f"(c[0]), "+f"(c[1]), "+f"(c[2]), "+f"(c[3])
        : "r"(a[0]), "r"(a[1]), "r"(a[2]), "r"(a[3]), "r"(b[0]), "r"(b[1]));
}
__device__ __forceinline__ void cpa16(uint32_t dst, const void* src, bool ok) {
    asm volatile("cp.async.ca.shared.global [%0], [%1], 16, %2;"
        :: "r"(dst), "l"(src), "r"(ok ? 16 : 0));
}
#define CPA_COMMIT() asm volatile("cp.async.commit_group;" ::: "memory")
#define CPA_WAIT(N)  asm volatile("cp.async.wait_group %0;" :: "n"(N) : "memory")

__device__ __forceinline__ uint32_t pack_bf2(float a, float b) {
    __nv_bfloat162 t = __floats2bfloat162_rn(a, b);
    return *reinterpret_cast<uint32_t*>(&t);
}
__device__ __forceinline__ void split4(float4 v, uint2& hv, uint2& lv) {
    bf16 h0 = __float2bfloat16(v.x), h1 = __float2bfloat16(v.y);
    bf16 h2 = __float2bfloat16(v.z), h3 = __float2bfloat16(v.w);
    float l0 = v.x - __bfloat162float(h0), l1 = v.y - __bfloat162float(h1);
    float l2 = v.z - __bfloat162float(h2), l3 = v.w - __bfloat162float(h3);
    __nv_bfloat162 p0 = __halves2bfloat162(h0, h1);
    __nv_bfloat162 p1 = __halves2bfloat162(h2, h3);
    hv = make_uint2(*reinterpret_cast<uint32_t*>(&p0), *reinterpret_cast<uint32_t*>(&p1));
    lv = make_uint2(pack_bf2(l0, l1), pack_bf2(l2, l3));
}
__device__ __forceinline__ float fast_tanh(float v) {
    v = fminf(fmaxf(v, -15.f), 15.f);
    const float t = __expf(2.f * v);
    return __fdividef(t - 1.f, t + 1.f);
}

// ======================= operand split kernels =============================
__global__ void split_plain(const float* __restrict__ src, bf16* __restrict__ h,
                            bf16* __restrict__ l, int n) {
    const int i = blockIdx.x * 256 + threadIdx.x;
    if (i >= n) return;
    const float v = src[i];
    const bf16 hb = __float2bfloat16(v);
    h[i] = hb;
    l[i] = __float2bfloat16(v - __bfloat162float(hb));
}
__global__ void split_w1(const float* __restrict__ W1) {
    const int i = blockIdx.x * 256 + threadIdx.x;
    if (i >= 64 * 32) return;
    const int r = i >> 5, k = i & 31;
    const float v = (k < 27) ? W1[r * 27 + k] : 0.f;
    const bf16 hb = __float2bfloat16(v);
    g_W1h[i] = hb;
    g_W1l[i] = __float2bfloat16(v - __bfloat162float(hb));
}
__global__ void split_wat(const float* __restrict__ Wa) {
    __shared__ float t[32][33];
    const int n = blockIdx.z;
    const int i0 = blockIdx.x * 32, h0 = blockIdx.y * 32;
    const int tx = threadIdx.x, ty = threadIdx.y;
    const float* W = Wa + (size_t)n * 336 * 600;
    #pragma unroll
    for (int j = 0; j < 32; j += 8) {
        const int i2 = i0 + ty + j, hh = h0 + tx;
        t[ty + j][tx] = (i2 < 336 && hh < 600) ? W[i2 * 600 + hh] : 0.f;
    }
    __syncthreads();
    bf16* Hh = g_Wath + (size_t)n * 600 * 336;
    bf16* Hl = g_Watl + (size_t)n * 600 * 336;
    #pragma unroll
    for (int j = 0; j < 32; j += 8) {
        const int hh = h0 + ty + j, i2 = i0 + tx;
        if (hh < 600 && i2 < 336) {
            const float v = t[tx][ty + j];
            const bf16 hb = __float2bfloat16(v);
            Hh[hh * 336 + i2] = hb;
            Hl[hh * 336 + i2] = __float2bfloat16(v - __bfloat162float(hb));
        }
    }
}
__global__ void transpose_kernel(const float* __restrict__ x) {
    __shared__ float tile[32][33];
    const int p0 = blockIdx.x * 32;
    const int b0 = blockIdx.y * 32;
    const int tx = threadIdx.x, ty = threadIdx.y;
    #pragma unroll
    for (int i = 0; i < 32; i += 8) {
        int p = p0 + tx, b = b0 + ty + i;
        if (p < 1200) tile[ty + i][tx] = x[(size_t)b * 1200 + p];
    }
    __syncthreads();
    #pragma unroll
    for (int i = 0; i < 32; i += 8) {
        int p = p0 + ty + i, b = b0 + tx;
        if (p < 1200) {
            const float v = tile[tx][ty + i];
            const bf16 hb = __float2bfloat16(v);
            g_Xth[(size_t)p * BATCH + b] = hb;
            g_Xtl[(size_t)p * BATCH + b] = __float2bfloat16(v - __bfloat162float(hb));
        }
    }
}

// ======================= pipelined mma.sync split-bf16 GEMM =================
// Tile M=128 x N=64 x K=32, 2-stage cp.async pipeline.
constexpr int ASTR = 40;
constexpr int BSTR = 72;
constexpr uint32_t OFF_AH = 0;
constexpr uint32_t OFF_AL = 128 * ASTR * 2;            // 10240
constexpr uint32_t OFF_BH = 2 * 128 * ASTR * 2;        // 20480
constexpr uint32_t OFF_BL = OFF_BH + 32 * BSTR * 2;    // 25088
constexpr uint32_t STAGE_B = OFF_BL + 32 * BSTR * 2;   // 29696
constexpr uint32_t SMEM_TOT = 2 * STAGE_B;             // 59392

template<int MODE, int OUTBF>
__global__ void __launch_bounds__(256, 2)
mma_gemm(const bf16* __restrict__ Ah, const bf16* __restrict__ Al,
         const bf16* __restrict__ Bh, const bf16* __restrict__ Bl,
         float* __restrict__ Cf, bf16* __restrict__ Ch, bf16* __restrict__ Cl,
         int K, int Kvalid, int Cout, int H, int W, int astr,
         const float* __restrict__ bnb, const float* __restrict__ bng,
         const float* __restrict__ bnbe, const float* __restrict__ bnm,
         const float* __restrict__ bnv, const float* __restrict__ bias)
{
    extern __shared__ __align__(16) char smem[];
    const uint32_t ubase = s2u(smem);

    const int tid = threadIdx.x, wid = tid >> 5, lid = tid & 31;
    const int yb   = blockIdx.x;
    const int bofs = blockIdx.y * 64;
    const int row0 = blockIdx.z * 128;
    const int wm = wid >> 1, wn = wid & 1;

    int oy = 0, ox = 0;
    if (MODE == 0) { oy = yb / W; ox = yb - oy * W; }
    const bf16* Abh = Ah;
    const bf16* Abl = Al;
    if (MODE == 1) { Abh += (size_t)yb * 600 * 336 + 80; Abl += (size_t)yb * 600 * 336 + 80; }
    if (MODE == 2) { Abh += (size_t)yb * 600 * 336;      Abl += (size_t)yb * 600 * 336; }

    // producer index precompute
    const int pr  = tid >> 1;               // A row 0..127
    const int pkk = (tid & 1) * 16;         // A col half
    const bool pok = (row0 + pr) < Cout;
    const int bk  = tid >> 3;               // B k row 0..31
    const int bseg = (tid & 7) * 8;         // B col seg

    const int nch = K / 32;

    auto issue = [&](int kc) {
        const uint32_t sb = ubase + (kc & 1) * STAGE_B;
        const int k0 = kc * 32;
        // A tiles
        {
            const bf16* ph = Abh + (size_t)(row0 + pr) * astr + k0 + pkk;
            const bf16* pl = Abl + (size_t)(row0 + pr) * astr + k0 + pkk;
            const uint32_t d = sb + (uint32_t)(pr * ASTR + pkk) * 2;
            cpa16(d + OFF_AH,      ph,     pok);
            cpa16(d + OFF_AH + 16, ph + 8, pok);
            cpa16(d + OFF_AL,      pl,     pok);
            cpa16(d + OFF_AL + 16, pl + 8, pok);
        }
        // B tiles (gathered)
        {
            const int kk = k0 + bk;
            bool ok = false;
            size_t rowoff = 0;
            if (MODE == 0) {
                if (kk < Kvalid) {
                    const int ci = kk / 9, r9 = kk - ci * 9;
                    const int ky = r9 / 3, kx = r9 - ky * 3;
                    const int iy = oy + ky - 1, ix = ox + kx - 1;
                    if ((unsigned)iy < (unsigned)H && (unsigned)ix < (unsigned)W) {
                        ok = true;
                        rowoff = (size_t)((ci * H + iy) * W + ix) * BATCH;
                    }
                }
            } else if (MODE == 1) {
                ok = true;
                rowoff = ((size_t)kk * NNODES + yb) * BATCH;
            } else {
                if (kk < Kvalid) {
                    const int slot = kk / 10, cc = kk - slot * 10;
                    const int mn = g_NEI[yb * 8 + slot];
                    if (mn >= 0) { ok = true; rowoff = (size_t)(mn * 10 + cc) * BATCH; }
                }
            }
            const uint32_t d = sb + (uint32_t)(bk * BSTR + bseg) * 2;
            cpa16(d + OFF_BH, Bh + rowoff + bofs + bseg, ok);
            cpa16(d + OFF_BL, Bl + rowoff + bofs + bseg, ok);
        }
        CPA_COMMIT();
    };

    float acc[2][4][4];
    #pragma unroll
    for (int a = 0; a < 2; ++a)
        #pragma unroll
        for (int b = 0; b < 4; ++b)
            #pragma unroll
            for (int c = 0; c < 4; ++c) acc[a][b][c] = 0.f;

    issue(0);
    for (int kc = 0; kc < nch; ++kc) {
        if (kc + 1 < nch) { issue(kc + 1); CPA_WAIT(1); }
        else              { CPA_WAIT(0); }
        __syncthreads();

        const uint32_t sb = ubase + (kc & 1) * STAGE_B;
        const uint32_t uAh = sb + OFF_AH, uAl = sb + OFF_AL;
        const uint32_t uBh = sb + OFF_BH, uBl = sb + OFF_BL;

        #pragma unroll
        for (int ks = 0; ks < 2; ++ks) {
            uint32_t ah[2][4], al[2][4], bh[2][4], bl[2][4];
            #pragma unroll
            for (int mt = 0; mt < 2; ++mt) {
                const uint32_t off = (uint32_t)(wm * 32 + mt * 16 + (lid & 15)) * (ASTR * 2)
                                   + ks * 32 + (lid >> 4) * 16;
                ldsm4(ah[mt], uAh + off);
                ldsm4(al[mt], uAl + off);
            }
            #pragma unroll
            for (int ng = 0; ng < 2; ++ng) {
                const uint32_t off = (uint32_t)(ks * 16 + (lid & 15)) * (BSTR * 2)
                                   + (wn * 32 + ng * 16) * 2 + (lid >> 4) * 16;
                ldsm4t(bh[ng], uBh + off);
                ldsm4t(bl[ng], uBl + off);
            }
            #pragma unroll
            for (int mt = 0; mt < 2; ++mt) {
                #pragma unroll
                for (int nt = 0; nt < 4; ++nt) {
                    const int ng = nt >> 1, p = (nt & 1) * 2;
                    mma16816(acc[mt][nt], ah[mt], &bh[ng][p]);
                    mma16816(acc[mt][nt], ah[mt], &bl[ng][p]);
                    mma16816(acc[mt][nt], al[mt], &bh[ng][p]);
                }
            }
        }
        __syncthreads();
    }

    // ---------------- epilogue ----------------
    const int g  = lid >> 2;
    const int qc = (lid & 3) * 2;
    #pragma unroll
    for (int mt = 0; mt < 2; ++mt) {
        const int r0g = row0 + wm * 32 + mt * 16 + g;
        const int r1g = r0g + 8;
        const bool ok0 = r0g < Cout, ok1 = r1g < Cout;
        float al0 = 1.f, be0 = 0.f, al1 = 1.f, be1 = 0.f;
        if (MODE == 0) {
            if (ok0) {
                const float s0 = bng[r0g] * rsqrtf(bnv[r0g] + 1e-5f);
                al0 = s0; be0 = (bnb[r0g] - bnm[r0g]) * s0 + bnbe[r0g];
            }
            if (ok1) {
                const float s1 = bng[r1g] * rsqrtf(bnv[r1g] + 1e-5f);
                al1 = s1; be1 = (bnb[r1g] - bnm[r1g]) * s1 + bnbe[r1g];
            }
        } else if (MODE == 1) {
            if (ok0) be0 = bias[yb * 600 + r0g];
            if (ok1) be1 = bias[yb * 600 + r1g];
        }
        size_t off0, off1;
        if (MODE == 0) {
            off0 = ((size_t)r0g * H * W + yb) * BATCH + bofs;
            off1 = ((size_t)r1g * H * W + yb) * BATCH + bofs;
        } else {
            off0 = ((size_t)yb * 600 + r0g) * BATCH + bofs;
            off1 = ((size_t)yb * 600 + r1g) * BATCH + bofs;
        }
        #pragma unroll
        for (int nt = 0; nt < 4; ++nt) {
            const int col = wn * 32 + nt * 8 + qc;
            float2 v0, v1;
            v0.x = acc[mt][nt][0] * al0 + be0;  v0.y = acc[mt][nt][1] * al0 + be0;
            v1.x = acc[mt][nt][2] * al1 + be1;  v1.y = acc[mt][nt][3] * al1 + be1;
            if (MODE == 0) {
                v0.x = fmaxf(v0.x, 0.f); v0.y = fmaxf(v0.y, 0.f);
                v1.x = fmaxf(v1.x, 0.f); v1.y = fmaxf(v1.y, 0.f);
            }
            if (OUTBF) {
                if (ok0) {
                    const bf16 h0 = __float2bfloat16(v0.x), h1 = __float2bfloat16(v0.y);
                    __nv_bfloat162 hp = __halves2bfloat162(h0, h1);
                    *(uint32_t*)&Ch[off0 + col] = *reinterpret_cast<uint32_t*>(&hp);
                    *(uint32_t*)&Cl[off0 + col] =
                        pack_bf2(v0.x - __bfloat162float(h0), v0.y - __bfloat162float(h1));
                }
                if (ok1) {
                    const bf16 h0 = __float2bfloat16(v1.x), h1 = __float2bfloat16(v1.y);
                    __nv_bfloat162 hp = __halves2bfloat162(h0, h1);
                    *(uint32_t*)&Ch[off1 + col] = *reinterpret_cast<uint32_t*>(&hp);
                    *(uint32_t*)&Cl[off1 + col] =
                        pack_bf2(v1.x - __bfloat162float(h0), v1.y - __bfloat162float(h1));
                }
            } else {
                if (ok0) *(float2*)(Cf + off0 + col) = v0;
                if (ok1) *(float2*)(Cf + off1 + col) = v1;
            }
        }
    }
}

// ======================= SIMT kernels ======================================
__global__ void nei_init_kernel() {
    int i = threadIdx.x;
    if (i >= NNODES) return;
    const int w = 5, size = 25;
    int n[8]; int cnt = 0;
    if (i - w >= 0)                               n[cnt++] = i - w;
    if (i % w != 0)                               n[cnt++] = i - 1;
    if ((i + 1) % w != 0)                         n[cnt++] = i + 1;
    if (i + w < size)                             n[cnt++] = i + w;
    if (i - w - 1 >= 0 && i % w != 0)             n[cnt++] = i - w - 1;
    if (i - w + 1 >= 0 && (i + 1) % w != 0)       n[cnt++] = i - w + 1;
    if (i + w - 1 < size && i % w != 0)           n[cnt++] = i + w - 1;
    if (i + w + 1 < size && (i + 1) % w != 0)     n[cnt++] = i + w + 1;
    while (cnt < 8) n[cnt++] = -1;
    for (int j = 0; j < 8; ++j) g_NEI[i * 8 + j] = n[j];
}

__global__ void poolv_kernel(const float* __restrict__ In,
                             bf16* __restrict__ Oh, bf16* __restrict__ Ol,
                             int C, int Hi, int Wi, int Ho, int Wo)
{
    const size_t total = (size_t)C * Ho * Wo * (BATCH / 4);
    const size_t idx = (size_t)blockIdx.x * blockDim.x + threadIdx.x;
    if (idx >= total) return;
    const int b4 = (int)(idx & (BATCH / 4 - 1));
    size_t t = idx >> 11;
    const int ox = (int)(t % Wo); t /= Wo;
    const int oy = (int)(t % Ho); const int c = (int)(t / Ho);
    const float ninf = __int_as_float(0xff800000);
    float4 mx = make_float4(ninf, ninf, ninf, ninf);
    #pragma unroll
    for (int ky = 0; ky < 3; ++ky) {
        const int iy = 2 * oy - 1 + ky;
        if ((unsigned)iy >= (unsigned)Hi) continue;
        #pragma unroll
        for (int kx = 0; kx < 3; ++kx) {
            const int ix = 2 * ox - 1 + kx;
            if ((unsigned)ix >= (unsigned)Wi) continue;
            const float4 v = *(const float4*)(In + (size_t)((c * Hi + iy) * Wi + ix) * BATCH + b4 * 4);
            mx.x = fmaxf(mx.x, v.x); mx.y = fmaxf(mx.y, v.y);
            mx.z = fmaxf(mx.z, v.z); mx.w = fmaxf(mx.w, v.w);
        }
    }
    uint2 hv, lv;
    split4(mx, hv, lv);
    const size_t off = (size_t)((c * Ho + oy) * Wo + ox) * BATCH + b4 * 4;
    *(uint2*)&Oh[off] = hv;
    *(uint2*)&Ol[off] = lv;
}

template<int STAGE>
__global__ void __launch_bounds__(256)
head_kernel(const float* __restrict__ Fin, const float* __restrict__ Gin,
            const float* __restrict__ Wb, const float* __restrict__ bb,
            float* __restrict__ out)
{
    __shared__ float Wbs[6000];
    __shared__ float bbs[10];
    const int n = blockIdx.y;
    const int b = blockIdx.x * 256 + threadIdx.x;
    const float* Wbn = Wb + (size_t)n * 6000;
    for (int i = threadIdx.x; i < 6000; i += 256) Wbs[i] = Wbn[i];
    if (threadIdx.x < 10) bbs[threadIdx.x] = bb[n * 10 + threadIdx.x];
    __syncthreads();

    float acc[10];
    #pragma unroll
    for (int c = 0; c < 10; ++c) acc[c] = bbs[c];

    const float* Fp = Fin + (size_t)n * 600 * BATCH + b;
    const float* Gp = (STAGE == 2) ? (Gin + (size_t)n * 600 * BATCH + b) : nullptr;
    for (int h = 0; h < 600; ++h) {
        float v = Fp[(size_t)h * BATCH];
        if (STAGE == 2) v += Gp[(size_t)h * BATCH];
        v = fast_tanh(v);
        #pragma unroll
        for (int c = 0; c < 10; ++c) acc[c] = fmaf(v, Wbs[h * 10 + c], acc[c]);
    }
    float mx = acc[0];
    #pragma unroll
    for (int c = 1; c < 10; ++c) mx = fmaxf(mx, acc[c]);
    float s = 0.f;
    #pragma unroll
    for (int c = 0; c < 10; ++c) { acc[c] = expf(acc[c] - mx); s += acc[c]; }
    const float inv = 1.f / s;
    if (STAGE == 1) {
        #pragma unroll
        for (int c = 0; c < 10; ++c) {
            const float p = acc[c] * inv;
            const bf16 hb = __float2bfloat16(p);
            g_PRh[(size_t)(n * 10 + c) * BATCH + b] = hb;
            g_PRl[(size_t)(n * 10 + c) * BATCH + b] =
                __float2bfloat16(p - __bfloat162float(hb));
        }
    } else {
        #pragma unroll
        for (int c = 0; c < 10; ++c) out[((size_t)n * BATCH + b) * 10 + c] = acc[c] * inv;
    }
}

__global__ void mean_kernel(const float* __restrict__ second, float* __restrict__ mout) {
    const int idx = blockIdx.x * 256 + threadIdx.x;
    if (idx >= BATCH * 10) return;
    float s = 0.f;
    #pragma unroll
    for (int n = 0; n < NNODES; ++n) s += second[(size_t)n * BATCH * 10 + idx];
    mout[idx] = s * (1.f / 25.f);
}

// ---------------- launch ----------------------------------------------------
extern "C" void kernel_launch(void* const* d_in, const int* in_sizes, int n_in,
                              void* d_out, int out_size)
{
    const float* x  = (const float*)d_in[0];
    const float* W1 = (const float*)d_in[1];
    const float* b1 = (const float*)d_in[2];
    const float* g1 = (const float*)d_in[3];
    const float* be1= (const float*)d_in[4];
    const float* m1 = (const float*)d_in[5];
    const float* v1 = (const float*)d_in[6];
    const float* W2 = (const float*)d_in[7];
    const float* b2 = (const float*)d_in[8];
    const float* g2 = (const float*)d_in[9];
    const float* be2= (const float*)d_in[10];
    const float* m2 = (const float*)d_in[11];
    const float* v2 = (const float*)d_in[12];
    const float* W3 = (const float*)d_in[13];
    const float* b3 = (const float*)d_in[14];
    const float* g3 = (const float*)d_in[15];
    const float* be3= (const float*)d_in[16];
    const float* m3 = (const float*)d_in[17];
    const float* v3 = (const float*)d_in[18];
    const float* W4 = (const float*)d_in[19];
    const float* b4 = (const float*)d_in[20];
    const float* g4 = (const float*)d_in[21];
    const float* be4= (const float*)d_in[22];
    const float* m4 = (const float*)d_in[23];
    const float* v4 = (const float*)d_in[24];
    const float* Wa = (const float*)d_in[25];
    const float* ba = (const float*)d_in[26];
    const float* Wb = (const float*)d_in[27];
    const float* bb = (const float*)d_in[28];

    float *C1, *C2, *F, *G;
    cudaGetSymbolAddress((void**)&C1, g_C1);
    cudaGetSymbolAddress((void**)&C2, g_C2);
    cudaGetSymbolAddress((void**)&F,  g_F);
    cudaGetSymbolAddress((void**)&G,  g_G);
    bf16 *Xth, *Xtl, *P1h, *P1l, *P2h, *P2l, *C3h, *C3l, *C4h, *C4l, *PRh, *PRl;
    bf16 *W1h, *W1l, *W2h, *W2l, *W3h, *W3l, *W4h, *W4l, *Wath, *Watl;
    cudaGetSymbolAddress((void**)&Xth, g_Xth);  cudaGetSymbolAddress((void**)&Xtl, g_Xtl);
    cudaGetSymbolAddress((void**)&P1h, g_P1h);  cudaGetSymbolAddress((void**)&P1l, g_P1l);
    cudaGetSymbolAddress((void**)&P2h, g_P2h);  cudaGetSymbolAddress((void**)&P2l, g_P2l);
    cudaGetSymbolAddress((void**)&C3h, g_C3h);  cudaGetSymbolAddress((void**)&C3l, g_C3l);
    cudaGetSymbolAddress((void**)&C4h, g_C4h);  cudaGetSymbolAddress((void**)&C4l, g_C4l);
    cudaGetSymbolAddress((void**)&PRh, g_PRh);  cudaGetSymbolAddress((void**)&PRl, g_PRl);
    cudaGetSymbolAddress((void**)&W1h, g_W1h);  cudaGetSymbolAddress((void**)&W1l, g_W1l);
    cudaGetSymbolAddress((void**)&W2h, g_W2h);  cudaGetSymbolAddress((void**)&W2l, g_W2l);
    cudaGetSymbolAddress((void**)&W3h, g_W3h);  cudaGetSymbolAddress((void**)&W3l, g_W3l);
    cudaGetSymbolAddress((void**)&W4h, g_W4h);  cudaGetSymbolAddress((void**)&W4l, g_W4l);
    cudaGetSymbolAddress((void**)&Wath, g_Wath); cudaGetSymbolAddress((void**)&Watl, g_Watl);

    cudaFuncSetAttribute(mma_gemm<0,0>, cudaFuncAttributeMaxDynamicSharedMemorySize, SMEM_TOT);
    cudaFuncSetAttribute(mma_gemm<0,1>, cudaFuncAttributeMaxDynamicSharedMemorySize, SMEM_TOT);
    cudaFuncSetAttribute(mma_gemm<1,0>, cudaFuncAttributeMaxDynamicSharedMemorySize, SMEM_TOT);
    cudaFuncSetAttribute(mma_gemm<2,0>, cudaFuncAttributeMaxDynamicSharedMemorySize, SMEM_TOT);

    float* out = (float*)d_out;
    float* second = out + BATCH * 10;

    // --- launch order arranged so ncu (-s 5 -c 1) samples conv2 mma_gemm ---
    transpose_kernel<<<dim3(38, 256), dim3(32, 8)>>>(x);                     // 0
    split_w1<<<8, 256>>>(W1);                                                // 1
    split_plain<<<(128 * 576 + 255) / 256, 256>>>(W2, W2h, W2l, 128 * 576);  // 2
    mma_gemm<0, 0><<<dim3(400, 128, 1), 256, SMEM_TOT>>>(                    // 3: conv1
        W1h, W1l, Xth, Xtl, C1, nullptr, nullptr,
        32, 27, 64, 20, 20, 32, b1, g1, be1, m1, v1, nullptr);
    poolv_kernel<<<(int)(((size_t)64 * 100 * (BATCH / 4) + 255) / 256), 256>>>(
        C1, P1h, P1l, 64, 20, 20, 10, 10);                                   // 4
    mma_gemm<0, 0><<<dim3(100, 128, 1), 256, SMEM_TOT>>>(                    // 5: conv2 (sampled)
        W2h, W2l, P1h, P1l, C2, nullptr, nullptr,
        576, 576, 128, 10, 10, 576, b2, g2, be2, m2, v2, nullptr);
    nei_init_kernel<<<1, 32>>>();                                            // 6
    split_plain<<<(256 * 1152 + 255) / 256, 256>>>(W3, W3h, W3l, 256 * 1152);// 7
    split_plain<<<(256 * 2304 + 255) / 256, 256>>>(W4, W4h, W4l, 256 * 2304);// 8
    split_wat<<<dim3(11, 19, 25), dim3(32, 8)>>>(Wa);                        // 9
    poolv_kernel<<<(int)(((size_t)128 * 25 * (BATCH / 4) + 255) / 256), 256>>>(
        C2, P2h, P2l, 128, 10, 10, 5, 5);                                    // 10
    mma_gemm<0, 1><<<dim3(25, 128, 2), 256, SMEM_TOT>>>(                     // 11: conv3
        W3h, W3l, P2h, P2l, nullptr, C3h, C3l,
        1152, 1152, 256, 5, 5, 1152, b3, g3, be3, m3, v3, nullptr);
    mma_gemm<0, 1><<<dim3(25, 128, 2), 256, SMEM_TOT>>>(                     // 12: conv4
        W4h, W4l, C3h, C3l, nullptr, C4h, C4l,
        2304, 2304, 256, 5, 5, 2304, b4, g4, be4, m4, v4, nullptr);
    mma_gemm<1, 0><<<dim3(25, 128, 5), 256, SMEM_TOT>>>(                     // 13: F
        Wath, Watl, C4h, C4l, F, nullptr, nullptr,
        256, 256, 600, 0, 0, 336, nullptr, nullptr, nullptr, nullptr, nullptr, ba);
    head_kernel<1><<<dim3(32, 25), 256>>>(F, nullptr, Wb, bb, nullptr);      // 14
    mma_gemm<2, 0><<<dim3(25, 128, 5), 256, SMEM_TOT>>>(                     // 15: G
        Wath, Watl, PRh, PRl, G, nullptr, nullptr,
        96, 80, 600, 0, 0, 336, nullptr, nullptr, nullptr, nullptr, nullptr, nullptr);
    head_kernel<2><<<dim3(32, 25), 256>>>(F, G, Wb, bb, second);             // 16
    mean_kernel<<<(BATCH * 10 + 255) / 256, 256>>>(second, out);             // 17
}